// round 1
// baseline (speedup 1.0000x reference)
#include <cuda_runtime.h>
#include <cstdint>

// Problem constants
#define B_   16
#define NE_  512
#define NIN_ 1024
#define H_   16
#define HD_  64
#define MROWS 8192           // B_*NE_
#define KDIM 1024
#define NDIM 1024

// ---------------- scratch (device globals; no allocations allowed) ----------
__device__ float g_xn[(size_t)MROWS * NIN_];
__device__ float g_q [(size_t)MROWS * NIN_];   // [B,H,NE,HD]
__device__ float g_k [(size_t)MROWS * NIN_];
__device__ float g_v [(size_t)MROWS * NIN_];
__device__ float g_ao[(size_t)MROWS * NIN_];   // attention output, row-major [M,1024]
__device__ float g_o [(size_t)MROWS * NIN_];   // WO output, pre-norm2
__device__ int   g_mask_kind;                  // 0=u8/bool, 1=int32, 2=float32

// ---------------- mask dtype detector ---------------------------------------
__global__ void mask_detect_kernel(const unsigned char* __restrict__ m)
{
    __shared__ int c1s, c2s;
    if (threadIdx.x == 0) { c1s = 0; c2s = 0; }
    __syncthreads();
    int c1 = 0, c2 = 0;
    for (int i = threadIdx.x; i < 16384; i += 256) {
        unsigned char v = m[i];
        int r = i & 3;
        if (v && r != 0) c1++;
        if (v && r <= 1) c2++;
    }
    atomicAdd(&c1s, c1);
    atomicAdd(&c2s, c2);
    __syncthreads();
    if (threadIdx.x == 0)
        g_mask_kind = (c1s == 0) ? 1 : ((c2s == 0) ? 2 : 0);
}

// ---------------- layernorm (PyTorch-style: unbiased std, /(std+eps)) -------
__global__ void norm_kernel(const float* __restrict__ xin,
                            const float* __restrict__ alpha,
                            const float* __restrict__ bias,
                            float* __restrict__ yout,
                            int xg, int yg)
{
    const float* x = xg ? g_o : xin;
    float*       y = yg ? g_xn : yout;
    int row = blockIdx.x;
    const float* xr = x + (size_t)row * 1024;
    float*       yr = y + (size_t)row * 1024;
    int t = threadIdx.x;

    float v[4];
    float s = 0.f, ss = 0.f;
#pragma unroll
    for (int i = 0; i < 4; i++) {
        v[i] = xr[t + i * 256];
        s += v[i];
        ss += v[i] * v[i];
    }
#pragma unroll
    for (int o = 16; o; o >>= 1) {
        s  += __shfl_xor_sync(0xffffffffu, s,  o);
        ss += __shfl_xor_sync(0xffffffffu, ss, o);
    }
    __shared__ float red[32];
    int w = t >> 5, l = t & 31;
    if (l == 0) { red[w] = s; red[w + 8] = ss; }
    __syncthreads();
    if (w == 0) {
        float s2  = (l < 8) ? red[l]     : 0.f;
        float ss2 = (l < 8) ? red[l + 8] : 0.f;
#pragma unroll
        for (int o = 4; o; o >>= 1) {
            s2  += __shfl_xor_sync(0xffffffffu, s2,  o);
            ss2 += __shfl_xor_sync(0xffffffffu, ss2, o);
        }
        if (l == 0) { red[16] = s2; red[17] = ss2; }
    }
    __syncthreads();
    float mean = red[16] * (1.f / 1024.f);
    float var  = (red[17] - 1024.f * mean * mean) * (1.f / 1023.f);
    var = fmaxf(var, 0.f);
    float inv = 1.f / (sqrtf(var) + 1e-6f);
#pragma unroll
    for (int i = 0; i < 4; i++) {
        int c = t + i * 256;
        yr[c] = alpha[c] * (v[i] - mean) * inv + bias[c];
    }
}

// ---------------- SGEMM: C[M,N] = A[M,K] @ W[N,K]^T + bias ------------------
// BM=128, BN=64, BK=16, 256 threads, 8x4 register tile per thread.
// a_sel: 0 -> g_xn, 1 -> g_ao.  c_sel: 0/1/2 -> g_q/g_k/g_v (remapped layout),
// 3 -> g_o (row-major).
__global__ void __launch_bounds__(256)
gemm_kernel(int a_sel, const float* __restrict__ W,
            const float* __restrict__ bias, int c_sel)
{
    __shared__ float sA[16][128];
    __shared__ float sW[16][64];

    const float* A = (a_sel == 0) ? g_xn : g_ao;
    float* C;
    if (c_sel == 0) C = g_q;
    else if (c_sel == 1) C = g_k;
    else if (c_sel == 2) C = g_v;
    else C = g_o;
    const int remap = (c_sel < 3);

    int tid = threadIdx.x;
    int tx = tid & 15, ty = tid >> 4;
    int rowBase = blockIdx.y * 128;
    int colBase = blockIdx.x * 64;

    float acc[8][4] = {};

    for (int kb = 0; kb < KDIM; kb += 16) {
        // load A tile (128x16) transposed -> sA[k][m]
#pragma unroll
        for (int i = 0; i < 2; i++) {
            int f = tid + i * 256;          // 0..511
            int r = f >> 2;                 // 0..127
            int kq = f & 3;                 // 0..3
            float4 a = *(const float4*)(A + (size_t)(rowBase + r) * KDIM + kb + kq * 4);
            sA[kq * 4 + 0][r] = a.x;
            sA[kq * 4 + 1][r] = a.y;
            sA[kq * 4 + 2][r] = a.z;
            sA[kq * 4 + 3][r] = a.w;
        }
        // load W tile (64x16) transposed -> sW[k][n]
        {
            int f = tid;                    // 0..255
            int n = f >> 2;                 // 0..63
            int kq = f & 3;
            float4 wv = *(const float4*)(W + (size_t)(colBase + n) * KDIM + kb + kq * 4);
            sW[kq * 4 + 0][n] = wv.x;
            sW[kq * 4 + 1][n] = wv.y;
            sW[kq * 4 + 2][n] = wv.z;
            sW[kq * 4 + 3][n] = wv.w;
        }
        __syncthreads();
#pragma unroll
        for (int k = 0; k < 16; k++) {
            float4 a0 = *(const float4*)&sA[k][ty * 8];
            float4 a1 = *(const float4*)&sA[k][ty * 8 + 4];
            float4 w0 = *(const float4*)&sW[k][tx * 4];
            float ar[8] = {a0.x, a0.y, a0.z, a0.w, a1.x, a1.y, a1.z, a1.w};
            float wr[4] = {w0.x, w0.y, w0.z, w0.w};
#pragma unroll
            for (int i = 0; i < 8; i++)
#pragma unroll
                for (int j = 0; j < 4; j++)
                    acc[i][j] += ar[i] * wr[j];
        }
        __syncthreads();
    }

#pragma unroll
    for (int i = 0; i < 8; i++) {
        int m = rowBase + ty * 8 + i;
#pragma unroll
        for (int j = 0; j < 4; j++) {
            int n = colBase + tx * 4 + j;
            float val = acc[i][j] + bias[n];
            if (remap) {
                int b = m >> 9, e = m & 511;
                int h = n >> 6, d = n & 63;
                C[(((size_t)(b * 16 + h) * 512) + e) * 64 + d] = val;
            } else {
                C[(size_t)m * 1024 + n] = val;
            }
        }
    }
}

// ---------------- attention: per (b,h,32-q-tile) -----------------------------
// S = Q@K^T (mask -> -inf, *1/8), exact softmax over 512, write e, O = E@V.
#define QT 32
#define SST 520          // padded row stride for score tile
#define QKSTRIDE 68      // padded row stride for Q/K/V tiles
#define ATTN_SMEM ((QT * QKSTRIDE + 64 * QKSTRIDE + QT * SST + 32) * 4)

__global__ void __launch_bounds__(256)
attn_kernel(const unsigned char* __restrict__ maskp, float* __restrict__ e_out)
{
    extern __shared__ float sh[];
    float* sQ   = sh;                          // 32 x 68
    float* sK   = sQ + QT * QKSTRIDE;          // 64 x 68 (reused for V)
    float* sS   = sK + 64 * QKSTRIDE;          // 32 x 520
    float* sInv = sS + QT * SST;               // 32

    int qt = blockIdx.x, h = blockIdx.y, b = blockIdx.z;
    int tid = threadIdx.x;
    int tx = tid & 15, ty = tid >> 4;
    int q0 = qt * QT;
    int kind = g_mask_kind;

    const float* Q  = g_q + (size_t)(b * 16 + h) * 512 * 64;
    const float* Kp = g_k + (size_t)(b * 16 + h) * 512 * 64;
    const float* Vp = g_v + (size_t)(b * 16 + h) * 512 * 64;

    // load Q tile (32x64)
#pragma unroll
    for (int i = 0; i < 2; i++) {
        int f = tid + i * 256;
        int r = f >> 4;
        int c = (f & 15) * 4;
        *(float4*)&sQ[r * QKSTRIDE + c] =
            *(const float4*)(Q + (size_t)(q0 + r) * 64 + c);
    }

    const float NEGINF = __int_as_float(0xff800000);

    // ---- scores ----
    for (int kb = 0; kb < 512; kb += 64) {
        __syncthreads();
#pragma unroll
        for (int i = 0; i < 4; i++) {
            int f = tid + i * 256;
            int r = f >> 4;
            int c = (f & 15) * 4;
            *(float4*)&sK[r * QKSTRIDE + c] =
                *(const float4*)(Kp + (size_t)(kb + r) * 64 + c);
        }
        __syncthreads();

        float acc[2][4] = {};
#pragma unroll
        for (int d = 0; d < 64; d += 4) {
            float4 qv0 = *(const float4*)&sQ[(ty * 2) * QKSTRIDE + d];
            float4 qv1 = *(const float4*)&sQ[(ty * 2 + 1) * QKSTRIDE + d];
            float4 kv[4];
#pragma unroll
            for (int j = 0; j < 4; j++)
                kv[j] = *(const float4*)&sK[(tx * 4 + j) * QKSTRIDE + d];
#pragma unroll
            for (int j = 0; j < 4; j++) {
                acc[0][j] += qv0.x * kv[j].x + qv0.y * kv[j].y +
                             qv0.z * kv[j].z + qv0.w * kv[j].w;
                acc[1][j] += qv1.x * kv[j].x + qv1.y * kv[j].y +
                             qv1.z * kv[j].z + qv1.w * kv[j].w;
            }
        }
#pragma unroll
        for (int i = 0; i < 2; i++) {
            int r = ty * 2 + i;
#pragma unroll
            for (int j = 0; j < 4; j++) {
                int kk = kb + tx * 4 + j;
                size_t midx = ((size_t)b * 512 + (q0 + r)) * 512 + kk;
                bool mm;
                if (kind == 1)      mm = ((const int*)maskp)[midx] != 0;
                else if (kind == 2) mm = ((const float*)maskp)[midx] != 0.f;
                else                mm = maskp[midx] != 0;
                sS[r * SST + kk] = mm ? NEGINF : acc[i][j] * 0.125f;
            }
        }
    }
    __syncthreads();

    // ---- softmax (exact, two pass). 8 warps x 4 rows ----
    int w = tid >> 5, l = tid & 31;
#pragma unroll
    for (int rr = 0; rr < 4; rr++) {
        int r = w * 4 + rr;
        float m = NEGINF;
        for (int k = l; k < 512; k += 32) m = fmaxf(m, sS[r * SST + k]);
#pragma unroll
        for (int o = 16; o; o >>= 1) m = fmaxf(m, __shfl_xor_sync(0xffffffffu, m, o));
        float s = 0.f;
        for (int k = l; k < 512; k += 32) {
            float ev = __expf(sS[r * SST + k] - m);
            sS[r * SST + k] = ev;
            s += ev;
        }
#pragma unroll
        for (int o = 16; o; o >>= 1) s += __shfl_xor_sync(0xffffffffu, s, o);
        if (l == 0) sInv[r] = 1.f / s;
    }
    __syncthreads();

    // ---- write e (normalized) ----
    float* erow = e_out + (((size_t)(b * 16 + h) * 512) + q0) * 512;
    for (int f = tid; f < QT * 512; f += 256) {
        int r = f >> 9;
        int k = f & 511;
        erow[(size_t)r * 512 + k] = sS[r * SST + k] * sInv[r];
    }

    // ---- O = E @ V ----
    float oacc[2][4] = {};
    for (int kb = 0; kb < 512; kb += 64) {
        __syncthreads();
#pragma unroll
        for (int i = 0; i < 4; i++) {
            int f = tid + i * 256;
            int r = f >> 4;
            int c = (f & 15) * 4;
            *(float4*)&sK[r * QKSTRIDE + c] =
                *(const float4*)(Vp + (size_t)(kb + r) * 64 + c);
        }
        __syncthreads();
#pragma unroll 8
        for (int kk = 0; kk < 64; kk++) {
            float e0 = sS[(ty * 2) * SST + kb + kk];
            float e1 = sS[(ty * 2 + 1) * SST + kb + kk];
            float4 vv = *(const float4*)&sK[kk * QKSTRIDE + tx * 4];
            oacc[0][0] += e0 * vv.x; oacc[0][1] += e0 * vv.y;
            oacc[0][2] += e0 * vv.z; oacc[0][3] += e0 * vv.w;
            oacc[1][0] += e1 * vv.x; oacc[1][1] += e1 * vv.y;
            oacc[1][2] += e1 * vv.z; oacc[1][3] += e1 * vv.w;
        }
    }
#pragma unroll
    for (int i = 0; i < 2; i++) {
        int q = q0 + ty * 2 + i;
        float inv = sInv[ty * 2 + i];
#pragma unroll
        for (int j = 0; j < 4; j++)
            g_ao[((size_t)(b * 512 + q)) * 1024 + h * 64 + tx * 4 + j] =
                oacc[i][j] * inv;
    }
}

// ---------------- launch ------------------------------------------------------
extern "C" void kernel_launch(void* const* d_in, const int* in_sizes, int n_in,
                              void* d_out, int out_size)
{
    const float*         events = (const float*)d_in[0];
    const unsigned char* mask   = (const unsigned char*)d_in[1];
    const float*         n1a    = (const float*)d_in[2];
    const float*         n1b    = (const float*)d_in[3];
    const float*         wq     = (const float*)d_in[4];
    const float*         bq     = (const float*)d_in[5];
    const float*         wk     = (const float*)d_in[6];
    const float*         bk     = (const float*)d_in[7];
    const float*         wv     = (const float*)d_in[8];
    const float*         bv     = (const float*)d_in[9];
    const float*         wo     = (const float*)d_in[10];
    const float*         bo     = (const float*)d_in[11];
    const float*         n2a    = (const float*)d_in[12];
    const float*         n2b    = (const float*)d_in[13];

    float* out   = (float*)d_out;                       // [16,512,1024]
    float* e_out = out + (size_t)MROWS * 1024;          // [16,16,512,512]

    mask_detect_kernel<<<1, 256>>>(mask);

    norm_kernel<<<MROWS, 256>>>(events, n1a, n1b, nullptr, 0, 1);

    dim3 gg(16, 64);   // N/64, M/128
    gemm_kernel<<<gg, 256>>>(0, wq, bq, 0);
    gemm_kernel<<<gg, 256>>>(0, wk, bk, 1);
    gemm_kernel<<<gg, 256>>>(0, wv, bv, 2);

    cudaFuncSetAttribute(attn_kernel,
                         cudaFuncAttributeMaxDynamicSharedMemorySize, ATTN_SMEM);
    attn_kernel<<<dim3(16, 16, 16), 256, ATTN_SMEM>>>(mask, e_out);

    gemm_kernel<<<gg, 256>>>(1, wo, bo, 3);

    norm_kernel<<<MROWS, 256>>>(nullptr, n2a, n2b, out, 1, 0);
}

// round 2
// speedup vs baseline: 1.5797x; 1.5797x over previous
#include <cuda_runtime.h>
#include <cstdint>

// Problem constants
#define B_   16
#define NE_  512
#define NIN_ 1024
#define H_   16
#define HD_  64
#define MROWS 8192           // B_*NE_
#define KDIM 1024
#define NDIM 1024

// ---------------- scratch (device globals; no allocations allowed) ----------
__device__ float g_xn[(size_t)MROWS * NIN_];
__device__ float g_q [(size_t)MROWS * NIN_];   // [B,H,NE,HD]
__device__ float g_k [(size_t)MROWS * NIN_];
__device__ float g_v [(size_t)MROWS * NIN_];
__device__ float g_ao[(size_t)MROWS * NIN_];   // attention output, row-major [M,1024]
__device__ float g_o [(size_t)MROWS * NIN_];   // WO output, pre-norm2
__device__ int   g_mask_kind;                  // 0=u8/bool, 1=int32, 2=float32

// ---------------- mask dtype detector ---------------------------------------
__global__ void mask_detect_kernel(const unsigned char* __restrict__ m)
{
    __shared__ int c1s, c2s;
    if (threadIdx.x == 0) { c1s = 0; c2s = 0; }
    __syncthreads();
    int c1 = 0, c2 = 0;
    for (int i = threadIdx.x; i < 16384; i += 256) {
        unsigned char v = m[i];
        int r = i & 3;
        if (v && r != 0) c1++;
        if (v && r <= 1) c2++;
    }
    atomicAdd(&c1s, c1);
    atomicAdd(&c2s, c2);
    __syncthreads();
    if (threadIdx.x == 0)
        g_mask_kind = (c1s == 0) ? 1 : ((c2s == 0) ? 2 : 0);
}

// ---------------- layernorm (PyTorch-style: unbiased std, /(std+eps)) -------
__global__ void norm_kernel(const float* __restrict__ xin,
                            const float* __restrict__ alpha,
                            const float* __restrict__ bias,
                            float* __restrict__ yout,
                            int xg, int yg)
{
    const float* x = xg ? g_o : xin;
    float*       y = yg ? g_xn : yout;
    int row = blockIdx.x;
    const float* xr = x + (size_t)row * 1024;
    float*       yr = y + (size_t)row * 1024;
    int t = threadIdx.x;

    float v[4];
    float s = 0.f, ss = 0.f;
#pragma unroll
    for (int i = 0; i < 4; i++) {
        v[i] = xr[t + i * 256];
        s += v[i];
        ss += v[i] * v[i];
    }
#pragma unroll
    for (int o = 16; o; o >>= 1) {
        s  += __shfl_xor_sync(0xffffffffu, s,  o);
        ss += __shfl_xor_sync(0xffffffffu, ss, o);
    }
    __shared__ float red[32];
    int w = t >> 5, l = t & 31;
    if (l == 0) { red[w] = s; red[w + 8] = ss; }
    __syncthreads();
    if (w == 0) {
        float s2  = (l < 8) ? red[l]     : 0.f;
        float ss2 = (l < 8) ? red[l + 8] : 0.f;
#pragma unroll
        for (int o = 4; o; o >>= 1) {
            s2  += __shfl_xor_sync(0xffffffffu, s2,  o);
            ss2 += __shfl_xor_sync(0xffffffffu, ss2, o);
        }
        if (l == 0) { red[16] = s2; red[17] = ss2; }
    }
    __syncthreads();
    float mean = red[16] * (1.f / 1024.f);
    float var  = (red[17] - 1024.f * mean * mean) * (1.f / 1023.f);
    var = fmaxf(var, 0.f);
    float inv = 1.f / (sqrtf(var) + 1e-6f);
#pragma unroll
    for (int i = 0; i < 4; i++) {
        int c = t + i * 256;
        yr[c] = alpha[c] * (v[i] - mean) * inv + bias[c];
    }
}

// ---------------- tf32 tensor-core SGEMM ------------------------------------
// C[M,N] = A[M,K] @ W[N,K]^T + bias.  BM=128, BN=128, BK=32, 256 thr (8 warps),
// each warp does a 64x32 tile via m16n8k8 tf32 MMA. cp.async double buffer.
#define BM 128
#define BN 128
#define BK 32
#define TSTRIDE 36                         // padded float stride (bank-safe)
#define TILE_FLTS ((BM + BN) * TSTRIDE)    // one stage of smem (floats)
#define GEMM_SMEM (2 * TILE_FLTS * 4)      // bytes

__device__ __forceinline__ void cp16(float* dst, const float* src)
{
    uint32_t d = (uint32_t)__cvta_generic_to_shared(dst);
    asm volatile("cp.async.cg.shared.global [%0], [%1], 16;\n" :: "r"(d), "l"(src));
}
__device__ __forceinline__ uint32_t f2tf(float x)
{
    uint32_t r;
    asm("cvt.rna.tf32.f32 %0, %1;" : "=r"(r) : "f"(x));
    return r;
}
__device__ __forceinline__ void mma_tf32(float* c, const uint32_t* a, const uint32_t* b)
{
    asm volatile(
        "mma.sync.aligned.m16n8k8.row.col.f32.tf32.tf32.f32 "
        "{%0,%1,%2,%3}, {%4,%5,%6,%7}, {%8,%9}, {%0,%1,%2,%3};"
        : "+f"(c[0]), "+f"(c[1]), "+f"(c[2]), "+f"(c[3])
        : "r"(a[0]), "r"(a[1]), "r"(a[2]), "r"(a[3]), "r"(b[0]), "r"(b[1]));
}

__global__ void __launch_bounds__(256)
gemm_kernel(int a_sel, const float* __restrict__ W,
            const float* __restrict__ bias, int c_sel)
{
    extern __shared__ float sh[];

    const float* A = (a_sel == 0) ? g_xn : g_ao;
    float* C;
    if (c_sel == 0) C = g_q;
    else if (c_sel == 1) C = g_k;
    else if (c_sel == 2) C = g_v;
    else C = g_o;
    const int remap = (c_sel < 3);

    const int tid = threadIdx.x;
    const int rowBase = blockIdx.y * BM;
    const int colBase = blockIdx.x * BN;

    const int wid  = tid >> 5, lane = tid & 31;
    const int wm   = wid & 1,  wn   = wid >> 1;   // 2 x 4 warp grid
    const int m0   = wm * 64,  n0   = wn * 32;
    const int lr   = lane >> 2, lc  = lane & 3;

    // global tile bases
    const float* Ab = A + (size_t)rowBase * KDIM;
    const float* Wb = W + (size_t)colBase * KDIM;

    float acc[4][4][4];
#pragma unroll
    for (int i = 0; i < 4; i++)
#pragma unroll
        for (int j = 0; j < 4; j++)
#pragma unroll
            for (int q = 0; q < 4; q++) acc[i][j][q] = 0.f;

    // tile loader: 8 cp.async of 16B per thread
    auto loadTile = [&](int kt, int s) {
        float* sA = sh + s * TILE_FLTS;
        float* sW = sA + BM * TSTRIDE;
        const float* Asrc = Ab + kt * BK;
        const float* Wsrc = Wb + kt * BK;
#pragma unroll
        for (int i = 0; i < 4; i++) {
            int j = tid + i * 256;        // 0..1023
            int r = j >> 3;               // 0..127
            int c = (j & 7) * 4;          // float4 col
            cp16(sA + r * TSTRIDE + c, Asrc + (size_t)r * KDIM + c);
        }
#pragma unroll
        for (int i = 0; i < 4; i++) {
            int j = tid + i * 256;
            int r = j >> 3;
            int c = (j & 7) * 4;
            cp16(sW + r * TSTRIDE + c, Wsrc + (size_t)r * KDIM + c);
        }
    };

    const int NK = KDIM / BK;   // 32
    loadTile(0, 0);
    asm volatile("cp.async.commit_group;\n");

    for (int kt = 0; kt < NK; kt++) {
        if (kt + 1 < NK) loadTile(kt + 1, (kt + 1) & 1);
        asm volatile("cp.async.commit_group;\n");
        asm volatile("cp.async.wait_group 1;\n");
        __syncthreads();

        const float* sA = sh + (kt & 1) * TILE_FLTS;
        const float* sW = sA + BM * TSTRIDE;

#pragma unroll
        for (int k8 = 0; k8 < BK / 8; k8++) {
            const int kc = k8 * 8 + lc;
            uint32_t a[4][4], b[4][2];
#pragma unroll
            for (int mi = 0; mi < 4; mi++) {
                const float* p = sA + (m0 + 16 * mi + lr) * TSTRIDE + kc;
                a[mi][0] = f2tf(p[0]);
                a[mi][1] = f2tf(p[8 * TSTRIDE]);
                a[mi][2] = f2tf(p[4]);
                a[mi][3] = f2tf(p[8 * TSTRIDE + 4]);
            }
#pragma unroll
            for (int ni = 0; ni < 4; ni++) {
                const float* p = sW + (n0 + 8 * ni + lr) * TSTRIDE + kc;
                b[ni][0] = f2tf(p[0]);
                b[ni][1] = f2tf(p[4]);
            }
#pragma unroll
            for (int mi = 0; mi < 4; mi++)
#pragma unroll
                for (int ni = 0; ni < 4; ni++)
                    mma_tf32(acc[mi][ni], a[mi], b[ni]);
        }
        __syncthreads();
    }

    // epilogue
#pragma unroll
    for (int mi = 0; mi < 4; mi++) {
#pragma unroll
        for (int ni = 0; ni < 4; ni++) {
            int row0 = rowBase + m0 + 16 * mi + lr;
            int col0 = colBase + n0 + 8 * ni + 2 * lc;
            float b0 = bias[col0], b1 = bias[col0 + 1];
            float v00 = acc[mi][ni][0] + b0;
            float v01 = acc[mi][ni][1] + b1;
            float v10 = acc[mi][ni][2] + b0;
            float v11 = acc[mi][ni][3] + b1;
            if (remap) {
                int bidx = row0 >> 9, e = row0 & 511;
                int hh = col0 >> 6,  d = col0 & 63;
                size_t base0 = (((size_t)(bidx * 16 + hh) * 512) + e) * 64 + d;
                C[base0]     = v00;
                C[base0 + 1] = v01;
                size_t base1 = base0 + (size_t)8 * 64;   // row0+8, same b,h
                C[base1]     = v10;
                C[base1 + 1] = v11;
            } else {
                C[(size_t)row0 * NDIM + col0]           = v00;
                C[(size_t)row0 * NDIM + col0 + 1]       = v01;
                C[(size_t)(row0 + 8) * NDIM + col0]     = v10;
                C[(size_t)(row0 + 8) * NDIM + col0 + 1] = v11;
            }
        }
    }
}

// ---------------- attention: per (b,h,32-q-tile) -----------------------------
// S = Q@K^T (mask -> -inf, *1/8), exact softmax over 512, write e, O = E@V.
#define QT 32
#define SST 520          // padded row stride for score tile
#define QKSTRIDE 68      // padded row stride for Q/K/V tiles
#define ATTN_SMEM ((QT * QKSTRIDE + 64 * QKSTRIDE + QT * SST + 32) * 4)

__global__ void __launch_bounds__(256)
attn_kernel(const unsigned char* __restrict__ maskp, float* __restrict__ e_out)
{
    extern __shared__ float sh[];
    float* sQ   = sh;                          // 32 x 68
    float* sK   = sQ + QT * QKSTRIDE;          // 64 x 68 (reused for V)
    float* sS   = sK + 64 * QKSTRIDE;          // 32 x 520
    float* sInv = sS + QT * SST;               // 32

    int qt = blockIdx.x, h = blockIdx.y, b = blockIdx.z;
    int tid = threadIdx.x;
    int tx = tid & 15, ty = tid >> 4;
    int q0 = qt * QT;
    int kind = g_mask_kind;

    const float* Q  = g_q + (size_t)(b * 16 + h) * 512 * 64;
    const float* Kp = g_k + (size_t)(b * 16 + h) * 512 * 64;
    const float* Vp = g_v + (size_t)(b * 16 + h) * 512 * 64;

    // load Q tile (32x64)
#pragma unroll
    for (int i = 0; i < 2; i++) {
        int f = tid + i * 256;
        int r = f >> 4;
        int c = (f & 15) * 4;
        *(float4*)&sQ[r * QKSTRIDE + c] =
            *(const float4*)(Q + (size_t)(q0 + r) * 64 + c);
    }

    const float NEGINF = __int_as_float(0xff800000);

    // ---- scores ----
    for (int kb = 0; kb < 512; kb += 64) {
        __syncthreads();
#pragma unroll
        for (int i = 0; i < 4; i++) {
            int f = tid + i * 256;
            int r = f >> 4;
            int c = (f & 15) * 4;
            *(float4*)&sK[r * QKSTRIDE + c] =
                *(const float4*)(Kp + (size_t)(kb + r) * 64 + c);
        }
        __syncthreads();

        float acc[2][4] = {};
#pragma unroll
        for (int d = 0; d < 64; d += 4) {
            float4 qv0 = *(const float4*)&sQ[(ty * 2) * QKSTRIDE + d];
            float4 qv1 = *(const float4*)&sQ[(ty * 2 + 1) * QKSTRIDE + d];
            float4 kv[4];
#pragma unroll
            for (int j = 0; j < 4; j++)
                kv[j] = *(const float4*)&sK[(tx * 4 + j) * QKSTRIDE + d];
#pragma unroll
            for (int j = 0; j < 4; j++) {
                acc[0][j] += qv0.x * kv[j].x + qv0.y * kv[j].y +
                             qv0.z * kv[j].z + qv0.w * kv[j].w;
                acc[1][j] += qv1.x * kv[j].x + qv1.y * kv[j].y +
                             qv1.z * kv[j].z + qv1.w * kv[j].w;
            }
        }
#pragma unroll
        for (int i = 0; i < 2; i++) {
            int r = ty * 2 + i;
#pragma unroll
            for (int j = 0; j < 4; j++) {
                int kk = kb + tx * 4 + j;
                size_t midx = ((size_t)b * 512 + (q0 + r)) * 512 + kk;
                bool mm;
                if (kind == 1)      mm = ((const int*)maskp)[midx] != 0;
                else if (kind == 2) mm = ((const float*)maskp)[midx] != 0.f;
                else                mm = maskp[midx] != 0;
                sS[r * SST + kk] = mm ? NEGINF : acc[i][j] * 0.125f;
            }
        }
    }
    __syncthreads();

    // ---- softmax (exact, two pass). 8 warps x 4 rows ----
    int w = tid >> 5, l = tid & 31;
#pragma unroll
    for (int rr = 0; rr < 4; rr++) {
        int r = w * 4 + rr;
        float m = NEGINF;
        for (int k = l; k < 512; k += 32) m = fmaxf(m, sS[r * SST + k]);
#pragma unroll
        for (int o = 16; o; o >>= 1) m = fmaxf(m, __shfl_xor_sync(0xffffffffu, m, o));
        float s = 0.f;
        for (int k = l; k < 512; k += 32) {
            float ev = __expf(sS[r * SST + k] - m);
            sS[r * SST + k] = ev;
            s += ev;
        }
#pragma unroll
        for (int o = 16; o; o >>= 1) s += __shfl_xor_sync(0xffffffffu, s, o);
        if (l == 0) sInv[r] = 1.f / s;
    }
    __syncthreads();

    // ---- write e (normalized) ----
    float* erow = e_out + (((size_t)(b * 16 + h) * 512) + q0) * 512;
    for (int f = tid; f < QT * 512; f += 256) {
        int r = f >> 9;
        int k = f & 511;
        erow[(size_t)r * 512 + k] = sS[r * SST + k] * sInv[r];
    }

    // ---- O = E @ V ----
    float oacc[2][4] = {};
    for (int kb = 0; kb < 512; kb += 64) {
        __syncthreads();
#pragma unroll
        for (int i = 0; i < 4; i++) {
            int f = tid + i * 256;
            int r = f >> 4;
            int c = (f & 15) * 4;
            *(float4*)&sK[r * QKSTRIDE + c] =
                *(const float4*)(Vp + (size_t)(kb + r) * 64 + c);
        }
        __syncthreads();
#pragma unroll 8
        for (int kk = 0; kk < 64; kk++) {
            float e0 = sS[(ty * 2) * SST + kb + kk];
            float e1 = sS[(ty * 2 + 1) * SST + kb + kk];
            float4 vv = *(const float4*)&sK[kk * QKSTRIDE + tx * 4];
            oacc[0][0] += e0 * vv.x; oacc[0][1] += e0 * vv.y;
            oacc[0][2] += e0 * vv.z; oacc[0][3] += e0 * vv.w;
            oacc[1][0] += e1 * vv.x; oacc[1][1] += e1 * vv.y;
            oacc[1][2] += e1 * vv.z; oacc[1][3] += e1 * vv.w;
        }
    }
#pragma unroll
    for (int i = 0; i < 2; i++) {
        int q = q0 + ty * 2 + i;
        float inv = sInv[ty * 2 + i];
#pragma unroll
        for (int j = 0; j < 4; j++)
            g_ao[((size_t)(b * 512 + q)) * 1024 + h * 64 + tx * 4 + j] =
                oacc[i][j] * inv;
    }
}

// ---------------- launch ------------------------------------------------------
extern "C" void kernel_launch(void* const* d_in, const int* in_sizes, int n_in,
                              void* d_out, int out_size)
{
    const float*         events = (const float*)d_in[0];
    const unsigned char* mask   = (const unsigned char*)d_in[1];
    const float*         n1a    = (const float*)d_in[2];
    const float*         n1b    = (const float*)d_in[3];
    const float*         wq     = (const float*)d_in[4];
    const float*         bq     = (const float*)d_in[5];
    const float*         wk     = (const float*)d_in[6];
    const float*         bk     = (const float*)d_in[7];
    const float*         wv     = (const float*)d_in[8];
    const float*         bv     = (const float*)d_in[9];
    const float*         wo     = (const float*)d_in[10];
    const float*         bo     = (const float*)d_in[11];
    const float*         n2a    = (const float*)d_in[12];
    const float*         n2b    = (const float*)d_in[13];

    float* out   = (float*)d_out;                       // [16,512,1024]
    float* e_out = out + (size_t)MROWS * 1024;          // [16,16,512,512]

    mask_detect_kernel<<<1, 256>>>(mask);

    norm_kernel<<<MROWS, 256>>>(events, n1a, n1b, nullptr, 0, 1);

    cudaFuncSetAttribute(gemm_kernel,
                         cudaFuncAttributeMaxDynamicSharedMemorySize, GEMM_SMEM);
    dim3 gg(NDIM / BN, MROWS / BM);   // (8, 64)
    gemm_kernel<<<gg, 256, GEMM_SMEM>>>(0, wq, bq, 0);
    gemm_kernel<<<gg, 256, GEMM_SMEM>>>(0, wk, bk, 1);
    gemm_kernel<<<gg, 256, GEMM_SMEM>>>(0, wv, bv, 2);

    cudaFuncSetAttribute(attn_kernel,
                         cudaFuncAttributeMaxDynamicSharedMemorySize, ATTN_SMEM);
    attn_kernel<<<dim3(16, 16, 16), 256, ATTN_SMEM>>>(mask, e_out);

    gemm_kernel<<<gg, 256, GEMM_SMEM>>>(1, wo, bo, 3);

    norm_kernel<<<MROWS, 256>>>(nullptr, n2a, n2b, out, 1, 0);
}

// round 3
// speedup vs baseline: 3.5518x; 2.2484x over previous
#include <cuda_runtime.h>
#include <cstdint>

// Problem constants
#define B_   16
#define NE_  512
#define NIN_ 1024
#define H_   16
#define HD_  64
#define MROWS 8192           // B_*NE_
#define KDIM 1024
#define NDIM 1024

// ---------------- scratch (device globals; no allocations allowed) ----------
__device__ float g_xn[(size_t)MROWS * NIN_];
__device__ float g_q [(size_t)MROWS * NIN_];   // [B,H,NE,HD]
__device__ float g_k [(size_t)MROWS * NIN_];
__device__ float g_v [(size_t)MROWS * NIN_];
__device__ float g_ao[(size_t)MROWS * NIN_];   // attention output, row-major [M,1024]
__device__ float g_o [(size_t)MROWS * NIN_];   // WO output, pre-norm2
__device__ float g_wr[(size_t)4 * KDIM * NDIM];// tf32-rounded weights (WQ,WK,WV,WO)
__device__ unsigned char g_mask8[(size_t)B_ * NE_ * NE_];
__device__ int   g_mask_kind;                  // 0=u8/bool, 1=int32, 2=float32

// ---------------- helpers ----------------------------------------------------
__device__ __forceinline__ void cp16(float* dst, const float* src)
{
    uint32_t d = (uint32_t)__cvta_generic_to_shared(dst);
    asm volatile("cp.async.cg.shared.global [%0], [%1], 16;\n" :: "r"(d), "l"(src));
}
__device__ __forceinline__ uint32_t f2tf(float x)
{
    uint32_t r;
    asm("cvt.rna.tf32.f32 %0, %1;" : "=r"(r) : "f"(x));
    return r;
}
__device__ __forceinline__ float f2tff(float x)
{
    return __uint_as_float(f2tf(x));
}
__device__ __forceinline__ void mma_tf32(float* c, const uint32_t* a, const uint32_t* b)
{
    asm volatile(
        "mma.sync.aligned.m16n8k8.row.col.f32.tf32.tf32.f32 "
        "{%0,%1,%2,%3}, {%4,%5,%6,%7}, {%8,%9}, {%0,%1,%2,%3};"
        : "+f"(c[0]), "+f"(c[1]), "+f"(c[2]), "+f"(c[3])
        : "r"(a[0]), "r"(a[1]), "r"(a[2]), "r"(a[3]), "r"(b[0]), "r"(b[1]));
}

// ---------------- mask dtype detector ---------------------------------------
__global__ void mask_detect_kernel(const unsigned char* __restrict__ m)
{
    __shared__ int c1s, c2s;
    if (threadIdx.x == 0) { c1s = 0; c2s = 0; }
    __syncthreads();
    int c1 = 0, c2 = 0;
    for (int i = threadIdx.x; i < 16384; i += 256) {
        unsigned char v = m[i];
        int r = i & 3;
        if (v && r != 0) c1++;
        if (v && r <= 1) c2++;
    }
    atomicAdd(&c1s, c1);
    atomicAdd(&c2s, c2);
    __syncthreads();
    if (threadIdx.x == 0)
        g_mask_kind = (c1s == 0) ? 1 : ((c2s == 0) ? 2 : 0);
}

// ---------------- mask -> u8 convert -----------------------------------------
__global__ void mask_convert_kernel(const unsigned char* __restrict__ m)
{
    int kind = g_mask_kind;
    size_t i = ((size_t)blockIdx.x * 256 + threadIdx.x) * 4;
    uchar4 o;
    if (kind == 1) {
        int4 v = *(const int4*)((const int*)m + i);
        o.x = v.x != 0; o.y = v.y != 0; o.z = v.z != 0; o.w = v.w != 0;
    } else if (kind == 2) {
        float4 v = *(const float4*)((const float*)m + i);
        o.x = v.x != 0.f; o.y = v.y != 0.f; o.z = v.z != 0.f; o.w = v.w != 0.f;
    } else {
        uchar4 v = *(const uchar4*)(m + i);
        o.x = v.x != 0; o.y = v.y != 0; o.z = v.z != 0; o.w = v.w != 0;
    }
    *(uchar4*)(g_mask8 + i) = o;
}

// ---------------- weight tf32 pre-round --------------------------------------
__global__ void round_kernel(const float* __restrict__ src, int sel)
{
    float* dst = g_wr + (size_t)sel * KDIM * NDIM;
    size_t i = ((size_t)blockIdx.x * 256 + threadIdx.x) * 4;
    float4 v = *(const float4*)(src + i);
    v.x = f2tff(v.x); v.y = f2tff(v.y); v.z = f2tff(v.z); v.w = f2tff(v.w);
    *(float4*)(dst + i) = v;
}

// ---------------- layernorm (PyTorch-style: unbiased std, /(std+eps)) -------
__global__ void norm_kernel(const float* __restrict__ xin,
                            const float* __restrict__ alpha,
                            const float* __restrict__ bias,
                            float* __restrict__ yout,
                            int xg, int yg)
{
    const float* x = xg ? g_o : xin;
    float*       y = yg ? g_xn : yout;
    int row = blockIdx.x;
    const float* xr = x + (size_t)row * 1024;
    float*       yr = y + (size_t)row * 1024;
    int t = threadIdx.x;

    float v[4];
    float s = 0.f, ss = 0.f;
#pragma unroll
    for (int i = 0; i < 4; i++) {
        v[i] = xr[t + i * 256];
        s += v[i];
        ss += v[i] * v[i];
    }
#pragma unroll
    for (int o = 16; o; o >>= 1) {
        s  += __shfl_xor_sync(0xffffffffu, s,  o);
        ss += __shfl_xor_sync(0xffffffffu, ss, o);
    }
    __shared__ float red[32];
    int w = t >> 5, l = t & 31;
    if (l == 0) { red[w] = s; red[w + 8] = ss; }
    __syncthreads();
    if (w == 0) {
        float s2  = (l < 8) ? red[l]     : 0.f;
        float ss2 = (l < 8) ? red[l + 8] : 0.f;
#pragma unroll
        for (int o = 4; o; o >>= 1) {
            s2  += __shfl_xor_sync(0xffffffffu, s2,  o);
            ss2 += __shfl_xor_sync(0xffffffffu, ss2, o);
        }
        if (l == 0) { red[16] = s2; red[17] = ss2; }
    }
    __syncthreads();
    float mean = red[16] * (1.f / 1024.f);
    float var  = (red[17] - 1024.f * mean * mean) * (1.f / 1023.f);
    var = fmaxf(var, 0.f);
    float inv = 1.f / (sqrtf(var) + 1e-6f);
#pragma unroll
    for (int i = 0; i < 4; i++) {
        int c = t + i * 256;
        float r = alpha[c] * (v[i] - mean) * inv + bias[c];
        yr[c] = yg ? f2tff(r) : r;    // round when feeding a GEMM
    }
}

// ---------------- tf32 tensor-core SGEMM ------------------------------------
// C[M,N] = A[M,K] @ W[N,K]^T + bias. Operands pre-rounded to tf32 in gmem.
#define BM 128
#define BN 128
#define BK 32
#define TSTRIDE 36
#define TILE_FLTS ((BM + BN) * TSTRIDE)
#define GEMM_SMEM (2 * TILE_FLTS * 4)

__global__ void __launch_bounds__(256)
gemm_kernel(int a_sel, int w_sel,
            const float* __restrict__ bias, int c_sel)
{
    extern __shared__ float sh[];

    const float* A = (a_sel == 0) ? g_xn : g_ao;
    const float* W = g_wr + (size_t)w_sel * KDIM * NDIM;
    float* C;
    if (c_sel == 0) C = g_q;
    else if (c_sel == 1) C = g_k;
    else if (c_sel == 2) C = g_v;
    else C = g_o;
    const int remap = (c_sel < 3);

    const int tid = threadIdx.x;
    const int rowBase = blockIdx.y * BM;
    const int colBase = blockIdx.x * BN;

    const int wid  = tid >> 5, lane = tid & 31;
    const int wm   = wid & 1,  wn   = wid >> 1;
    const int m0   = wm * 64,  n0   = wn * 32;
    const int lr   = lane >> 2, lc  = lane & 3;

    const float* Ab = A + (size_t)rowBase * KDIM;
    const float* Wb = W + (size_t)colBase * KDIM;

    float acc[4][4][4];
#pragma unroll
    for (int i = 0; i < 4; i++)
#pragma unroll
        for (int j = 0; j < 4; j++)
#pragma unroll
            for (int q = 0; q < 4; q++) acc[i][j][q] = 0.f;

    auto loadTile = [&](int kt, int s) {
        float* sA = sh + s * TILE_FLTS;
        float* sW = sA + BM * TSTRIDE;
        const float* Asrc = Ab + kt * BK;
        const float* Wsrc = Wb + kt * BK;
#pragma unroll
        for (int i = 0; i < 4; i++) {
            int j = tid + i * 256;
            int r = j >> 3;
            int c = (j & 7) * 4;
            cp16(sA + r * TSTRIDE + c, Asrc + (size_t)r * KDIM + c);
        }
#pragma unroll
        for (int i = 0; i < 4; i++) {
            int j = tid + i * 256;
            int r = j >> 3;
            int c = (j & 7) * 4;
            cp16(sW + r * TSTRIDE + c, Wsrc + (size_t)r * KDIM + c);
        }
    };

    const int NK = KDIM / BK;
    loadTile(0, 0);
    asm volatile("cp.async.commit_group;\n");

    for (int kt = 0; kt < NK; kt++) {
        if (kt + 1 < NK) loadTile(kt + 1, (kt + 1) & 1);
        asm volatile("cp.async.commit_group;\n");
        asm volatile("cp.async.wait_group 1;\n");
        __syncthreads();

        const float* sA = sh + (kt & 1) * TILE_FLTS;
        const float* sW = sA + BM * TSTRIDE;

#pragma unroll
        for (int k8 = 0; k8 < BK / 8; k8++) {
            const int kc = k8 * 8 + lc;
            uint32_t a[4][4], b[4][2];
#pragma unroll
            for (int mi = 0; mi < 4; mi++) {
                const float* p = sA + (m0 + 16 * mi + lr) * TSTRIDE + kc;
                a[mi][0] = __float_as_uint(p[0]);
                a[mi][1] = __float_as_uint(p[8 * TSTRIDE]);
                a[mi][2] = __float_as_uint(p[4]);
                a[mi][3] = __float_as_uint(p[8 * TSTRIDE + 4]);
            }
#pragma unroll
            for (int ni = 0; ni < 4; ni++) {
                const float* p = sW + (n0 + 8 * ni + lr) * TSTRIDE + kc;
                b[ni][0] = __float_as_uint(p[0]);
                b[ni][1] = __float_as_uint(p[4]);
            }
#pragma unroll
            for (int mi = 0; mi < 4; mi++)
#pragma unroll
                for (int ni = 0; ni < 4; ni++)
                    mma_tf32(acc[mi][ni], a[mi], b[ni]);
        }
        __syncthreads();
    }

#pragma unroll
    for (int mi = 0; mi < 4; mi++) {
#pragma unroll
        for (int ni = 0; ni < 4; ni++) {
            int row0 = rowBase + m0 + 16 * mi + lr;
            int col0 = colBase + n0 + 8 * ni + 2 * lc;
            float b0 = bias[col0], b1 = bias[col0 + 1];
            float v00 = acc[mi][ni][0] + b0;
            float v01 = acc[mi][ni][1] + b1;
            float v10 = acc[mi][ni][2] + b0;
            float v11 = acc[mi][ni][3] + b1;
            if (remap) {
                // Q/K/V are consumed by tf32 MMA in attention: round now.
                v00 = f2tff(v00); v01 = f2tff(v01);
                v10 = f2tff(v10); v11 = f2tff(v11);
                int bidx = row0 >> 9, e = row0 & 511;
                int hh = col0 >> 6,  d = col0 & 63;
                size_t base0 = (((size_t)(bidx * 16 + hh) * 512) + e) * 64 + d;
                C[base0]     = v00;
                C[base0 + 1] = v01;
                size_t base1 = base0 + (size_t)8 * 64;
                C[base1]     = v10;
                C[base1 + 1] = v11;
            } else {
                C[(size_t)row0 * NDIM + col0]           = v00;
                C[(size_t)row0 * NDIM + col0 + 1]       = v01;
                C[(size_t)(row0 + 8) * NDIM + col0]     = v10;
                C[(size_t)(row0 + 8) * NDIM + col0 + 1] = v11;
            }
        }
    }
}

// ---------------- attention (tensor-core) ------------------------------------
// Per (b,h,32-q-tile): S = (Q/8)@K^T via tf32 MMA, masked softmax over 512,
// write e, O^T = V^T @ E^T via tf32 MMA. 256 threads, 2 CTAs/SM.
#define QT  32
#define KC  128
#define SST 520     // 520 % 32 == 8  -> conflict-free E-fragment reads
#define QS  68      // 68  % 32 == 4  -> conflict-free Q/K fragment reads
#define VS  72      // 72  % 32 == 8  -> conflict-free V^T fragment reads
#define ATTN_SMEM ((QT * QS + KC * VS + QT * SST + 32) * 4)

__global__ void __launch_bounds__(256, 2)
attn_kernel(float* __restrict__ e_out)
{
    extern __shared__ float sh[];
    float* sQ   = sh;                 // 32 x QS   (reused as sO)
    float* sKV  = sQ + QT * QS;       // 128 x VS  (K stride QS-like 68 / V stride 72)
    float* sS   = sKV + KC * VS;      // 32 x SST
    float* sInv = sS + QT * SST;      // 32

    const int qt = blockIdx.x, h = blockIdx.y, b = blockIdx.z;
    const int tid = threadIdx.x;
    const int lane = tid & 31, wid = tid >> 5;
    const int lr = lane >> 2, lc = lane & 3;
    const int q0 = qt * QT;

    const float* Q  = g_q + (size_t)(b * 16 + h) * 512 * 64;
    const float* Kp = g_k + (size_t)(b * 16 + h) * 512 * 64;
    const float* Vp = g_v + (size_t)(b * 16 + h) * 512 * 64;

    // ---- load Q tile scaled by 1/8 (power of 2: stays tf32-exact) ----
#pragma unroll
    for (int i = 0; i < 2; i++) {
        int f = tid + i * 256;
        int r = f >> 4;
        int c = (f & 15) * 4;
        float4 v = *(const float4*)(Q + (size_t)(q0 + r) * 64 + c);
        v.x *= 0.125f; v.y *= 0.125f; v.z *= 0.125f; v.w *= 0.125f;
        *(float4*)&sQ[r * QS + c] = v;
    }

    // ---- scores: S[32,512] ----
    const int wm = wid & 1, wn = wid >> 1;   // 2 x 4 warp grid
    for (int kb = 0; kb < 512; kb += KC) {
        __syncthreads();
#pragma unroll
        for (int i = 0; i < 8; i++) {
            int f = tid + i * 256;
            int r = f >> 4;
            int c = (f & 15) * 4;
            cp16(sKV + r * QS + c, Kp + (size_t)(kb + r) * 64 + c);
        }
        asm volatile("cp.async.commit_group;\n");
        asm volatile("cp.async.wait_group 0;\n");
        __syncthreads();

        float acc[4][4] = {};
#pragma unroll
        for (int k8 = 0; k8 < 8; k8++) {
            const int kc = k8 * 8 + lc;
            uint32_t a[4], bfr[4][2];
            const float* p = sQ + (wm * 16 + lr) * QS + kc;
            a[0] = __float_as_uint(p[0]);
            a[1] = __float_as_uint(p[8 * QS]);
            a[2] = __float_as_uint(p[4]);
            a[3] = __float_as_uint(p[8 * QS + 4]);
#pragma unroll
            for (int ni = 0; ni < 4; ni++) {
                const float* pk = sKV + (wn * 32 + ni * 8 + lr) * QS + kc;
                bfr[ni][0] = __float_as_uint(pk[0]);
                bfr[ni][1] = __float_as_uint(pk[4]);
            }
#pragma unroll
            for (int ni = 0; ni < 4; ni++)
                mma_tf32(acc[ni], a, bfr[ni]);
        }
        const int row = wm * 16 + lr;
#pragma unroll
        for (int ni = 0; ni < 4; ni++) {
            int col = kb + wn * 32 + ni * 8 + 2 * lc;
            sS[row * SST + col]             = acc[ni][0];
            sS[row * SST + col + 1]         = acc[ni][1];
            sS[(row + 8) * SST + col]       = acc[ni][2];
            sS[(row + 8) * SST + col + 1]   = acc[ni][3];
        }
    }
    __syncthreads();

    // ---- masked softmax (8 warps x 4 rows) ----
    const float NEGINF = __int_as_float(0xff800000);
    const unsigned char* mbase = g_mask8 + ((size_t)b * 512 + q0) * 512;
#pragma unroll
    for (int rr = 0; rr < 4; rr++) {
        int r = wid * 4 + rr;
        float* srow = sS + r * SST;
        const unsigned char* mr = mbase + (size_t)r * 512;
        unsigned int mbits = 0;
        float mx = NEGINF;
#pragma unroll
        for (int i = 0; i < 16; i++) {
            int k = lane + 32 * i;
            if (mr[k]) mbits |= (1u << i);
            else       mx = fmaxf(mx, srow[k]);
        }
#pragma unroll
        for (int o = 16; o; o >>= 1) mx = fmaxf(mx, __shfl_xor_sync(0xffffffffu, mx, o));
        float sum = 0.f;
#pragma unroll
        for (int i = 0; i < 16; i++) {
            int k = lane + 32 * i;
            float ev = (mbits >> i) & 1 ? 0.f : __expf(srow[k] - mx);
            srow[k] = ev;
            sum += ev;
        }
#pragma unroll
        for (int o = 16; o; o >>= 1) sum += __shfl_xor_sync(0xffffffffu, sum, o);
        if (lane == 0) sInv[r] = 1.f / sum;
    }
    __syncthreads();

    // ---- write e (normalized), coalesced float4 ----
    float* erow = e_out + (((size_t)(b * 16 + h) * 512) + q0) * 512;
#pragma unroll
    for (int i = 0; i < 16; i++) {
        int idx = tid + i * 256;
        int r = idx >> 7;
        int c = (idx & 127) * 4;
        float inv = sInv[r];
        float4 v = *(const float4*)&sS[r * SST + c];
        v.x *= inv; v.y *= inv; v.z *= inv; v.w *= inv;
        *(float4*)(erow + (size_t)r * 512 + c) = v;
    }

    // ---- O^T = V^T @ E^T ----
    const int wd = wid & 3, wq = wid >> 2;   // 4 d-blocks x 2 q-halves
    const int d0 = wd * 16, qb = wq * 16;
    float oacc[2][4] = {};
    for (int kb = 0; kb < 512; kb += KC) {
        __syncthreads();
#pragma unroll
        for (int i = 0; i < 8; i++) {
            int f = tid + i * 256;
            int r = f >> 4;
            int c = (f & 15) * 4;
            cp16(sKV + r * VS + c, Vp + (size_t)(kb + r) * 64 + c);
        }
        asm volatile("cp.async.commit_group;\n");
        asm volatile("cp.async.wait_group 0;\n");
        __syncthreads();

#pragma unroll
        for (int k8 = 0; k8 < KC / 8; k8++) {
            const int kc = k8 * 8 + lc;
            uint32_t a[4], bfr[2][2];
            const float* pv = sKV + kc * VS + d0 + lr;
            a[0] = __float_as_uint(pv[0]);
            a[1] = __float_as_uint(pv[8]);
            a[2] = __float_as_uint(pv[4 * VS]);
            a[3] = __float_as_uint(pv[4 * VS + 8]);
#pragma unroll
            for (int ni = 0; ni < 2; ni++) {
                const float* pe = sS + (qb + ni * 8 + lr) * SST + kb + kc;
                bfr[ni][0] = f2tf(pe[0]);
                bfr[ni][1] = f2tf(pe[4]);
            }
#pragma unroll
            for (int ni = 0; ni < 2; ni++)
                mma_tf32(oacc[ni], a, bfr[ni]);
        }
    }
    __syncthreads();

    // ---- normalize, stage O[q][d] in smem (reuse sQ), write coalesced ----
    float* sO = sQ;
#pragma unroll
    for (int ni = 0; ni < 2; ni++) {
        int q = qb + ni * 8 + 2 * lc;
        float i0 = sInv[q], i1 = sInv[q + 1];
        sO[q * QS + d0 + lr]           = oacc[ni][0] * i0;
        sO[(q + 1) * QS + d0 + lr]     = oacc[ni][1] * i1;
        sO[q * QS + d0 + lr + 8]       = oacc[ni][2] * i0;
        sO[(q + 1) * QS + d0 + lr + 8] = oacc[ni][3] * i1;
    }
    __syncthreads();
#pragma unroll
    for (int i = 0; i < 2; i++) {
        int f = tid + i * 256;
        int r = f >> 4;
        int c = (f & 15) * 4;
        float4 v = *(const float4*)&sO[r * QS + c];
        v.x = f2tff(v.x); v.y = f2tff(v.y); v.z = f2tff(v.z); v.w = f2tff(v.w);
        *(float4*)(g_ao + ((size_t)(b * 512 + q0 + r)) * 1024 + h * 64 + c) = v;
    }
}

// ---------------- launch ------------------------------------------------------
extern "C" void kernel_launch(void* const* d_in, const int* in_sizes, int n_in,
                              void* d_out, int out_size)
{
    const float*         events = (const float*)d_in[0];
    const unsigned char* mask   = (const unsigned char*)d_in[1];
    const float*         n1a    = (const float*)d_in[2];
    const float*         n1b    = (const float*)d_in[3];
    const float*         wq     = (const float*)d_in[4];
    const float*         bq     = (const float*)d_in[5];
    const float*         wk     = (const float*)d_in[6];
    const float*         bk     = (const float*)d_in[7];
    const float*         wv     = (const float*)d_in[8];
    const float*         bv     = (const float*)d_in[9];
    const float*         wo     = (const float*)d_in[10];
    const float*         bo     = (const float*)d_in[11];
    const float*         n2a    = (const float*)d_in[12];
    const float*         n2b    = (const float*)d_in[13];

    float* out   = (float*)d_out;                       // [16,512,1024]
    float* e_out = out + (size_t)MROWS * 1024;          // [16,16,512,512]

    mask_detect_kernel<<<1, 256>>>(mask);
    mask_convert_kernel<<<4096, 256>>>(mask);

    round_kernel<<<1024, 256>>>(wq, 0);
    round_kernel<<<1024, 256>>>(wk, 1);
    round_kernel<<<1024, 256>>>(wv, 2);
    round_kernel<<<1024, 256>>>(wo, 3);

    norm_kernel<<<MROWS, 256>>>(events, n1a, n1b, nullptr, 0, 1);

    cudaFuncSetAttribute(gemm_kernel,
                         cudaFuncAttributeMaxDynamicSharedMemorySize, GEMM_SMEM);
    dim3 gg(NDIM / BN, MROWS / BM);   // (8, 64)
    gemm_kernel<<<gg, 256, GEMM_SMEM>>>(0, 0, bq, 0);
    gemm_kernel<<<gg, 256, GEMM_SMEM>>>(0, 1, bk, 1);
    gemm_kernel<<<gg, 256, GEMM_SMEM>>>(0, 2, bv, 2);

    cudaFuncSetAttribute(attn_kernel,
                         cudaFuncAttributeMaxDynamicSharedMemorySize, ATTN_SMEM);
    attn_kernel<<<dim3(16, 16, 16), 256, ATTN_SMEM>>>(e_out);

    gemm_kernel<<<gg, 256, GEMM_SMEM>>>(1, 3, bo, 3);

    norm_kernel<<<MROWS, 256>>>(nullptr, n2a, n2b, out, 1, 0);
}

// round 4
// speedup vs baseline: 3.7097x; 1.0445x over previous
#include <cuda_runtime.h>
#include <cstdint>

// Problem constants
#define B_   16
#define NE_  512
#define NIN_ 1024
#define H_   16
#define HD_  64
#define MROWS 8192           // B_*NE_
#define KDIM 1024
#define NDIM 1024

// ---------------- scratch (device globals; no allocations allowed) ----------
__device__ float g_xn[(size_t)MROWS * NIN_];
__device__ float g_q [(size_t)MROWS * NIN_];   // [B,H,NE,HD]
__device__ float g_k [(size_t)MROWS * NIN_];
__device__ float g_v [(size_t)MROWS * NIN_];
__device__ float g_ao[(size_t)MROWS * NIN_];   // attention output, row-major [M,1024]
__device__ float g_o [(size_t)MROWS * NIN_];   // WO output, pre-norm2
__device__ float g_wr[(size_t)4 * KDIM * NDIM];// tf32-rounded weights (WQ,WK,WV,WO)
__device__ unsigned char g_mask8[(size_t)B_ * NE_ * NE_];
__device__ int   g_mask_kind;                  // 0=u8/bool, 1=int32, 2=float32

// ---------------- helpers ----------------------------------------------------
__device__ __forceinline__ void cp16(float* dst, const float* src)
{
    uint32_t d = (uint32_t)__cvta_generic_to_shared(dst);
    asm volatile("cp.async.cg.shared.global [%0], [%1], 16;\n" :: "r"(d), "l"(src));
}
__device__ __forceinline__ uint32_t f2tf(float x)
{
    uint32_t r;
    asm("cvt.rna.tf32.f32 %0, %1;" : "=r"(r) : "f"(x));
    return r;
}
__device__ __forceinline__ float f2tff(float x)
{
    return __uint_as_float(f2tf(x));
}
__device__ __forceinline__ void mma_tf32(float* c, const uint32_t* a, const uint32_t* b)
{
    asm volatile(
        "mma.sync.aligned.m16n8k8.row.col.f32.tf32.tf32.f32 "
        "{%0,%1,%2,%3}, {%4,%5,%6,%7}, {%8,%9}, {%0,%1,%2,%3};"
        : "+f"(c[0]), "+f"(c[1]), "+f"(c[2]), "+f"(c[3])
        : "r"(a[0]), "r"(a[1]), "r"(a[2]), "r"(a[3]), "r"(b[0]), "r"(b[1]));
}

// ---------------- mask dtype detector ---------------------------------------
__global__ void mask_detect_kernel(const unsigned char* __restrict__ m)
{
    __shared__ int c1s, c2s;
    if (threadIdx.x == 0) { c1s = 0; c2s = 0; }
    __syncthreads();
    int c1 = 0, c2 = 0;
    for (int i = threadIdx.x; i < 16384; i += 256) {
        unsigned char v = m[i];
        int r = i & 3;
        if (v && r != 0) c1++;
        if (v && r <= 1) c2++;
    }
    atomicAdd(&c1s, c1);
    atomicAdd(&c2s, c2);
    __syncthreads();
    if (threadIdx.x == 0)
        g_mask_kind = (c1s == 0) ? 1 : ((c2s == 0) ? 2 : 0);
}

// ---------------- mask -> u8 convert -----------------------------------------
__global__ void mask_convert_kernel(const unsigned char* __restrict__ m)
{
    int kind = g_mask_kind;
    size_t i = ((size_t)blockIdx.x * 256 + threadIdx.x) * 4;
    uchar4 o;
    if (kind == 1) {
        int4 v = *(const int4*)((const int*)m + i);
        o.x = v.x != 0; o.y = v.y != 0; o.z = v.z != 0; o.w = v.w != 0;
    } else if (kind == 2) {
        float4 v = *(const float4*)((const float*)m + i);
        o.x = v.x != 0.f; o.y = v.y != 0.f; o.z = v.z != 0.f; o.w = v.w != 0.f;
    } else {
        uchar4 v = *(const uchar4*)(m + i);
        o.x = v.x != 0; o.y = v.y != 0; o.z = v.z != 0; o.w = v.w != 0;
    }
    *(uchar4*)(g_mask8 + i) = o;
}

// ---------------- weight tf32 pre-round (all 4 in one launch) ----------------
__global__ void round_kernel(const float* __restrict__ s0, const float* __restrict__ s1,
                             const float* __restrict__ s2, const float* __restrict__ s3)
{
    int sel = blockIdx.x >> 10;
    const float* src = sel == 0 ? s0 : sel == 1 ? s1 : sel == 2 ? s2 : s3;
    size_t base = (size_t)(blockIdx.x & 1023) * 256 + threadIdx.x;
    size_t i = base * 4;
    float* dst = g_wr + (size_t)sel * KDIM * NDIM;
    float4 v = *(const float4*)(src + i);
    v.x = f2tff(v.x); v.y = f2tff(v.y); v.z = f2tff(v.z); v.w = f2tff(v.w);
    *(float4*)(dst + i) = v;
}

// ---------------- layernorm (PyTorch-style: unbiased std, /(std+eps)) -------
__global__ void norm_kernel(const float* __restrict__ xin,
                            const float* __restrict__ alpha,
                            const float* __restrict__ bias,
                            float* __restrict__ yout,
                            int xg, int yg)
{
    const float* x = xg ? g_o : xin;
    float*       y = yg ? g_xn : yout;
    int row = blockIdx.x;
    const float* xr = x + (size_t)row * 1024;
    float*       yr = y + (size_t)row * 1024;
    int t = threadIdx.x;

    float v[4];
    float s = 0.f, ss = 0.f;
#pragma unroll
    for (int i = 0; i < 4; i++) {
        v[i] = xr[t + i * 256];
        s += v[i];
        ss += v[i] * v[i];
    }
#pragma unroll
    for (int o = 16; o; o >>= 1) {
        s  += __shfl_xor_sync(0xffffffffu, s,  o);
        ss += __shfl_xor_sync(0xffffffffu, ss, o);
    }
    __shared__ float red[32];
    int w = t >> 5, l = t & 31;
    if (l == 0) { red[w] = s; red[w + 8] = ss; }
    __syncthreads();
    if (w == 0) {
        float s2  = (l < 8) ? red[l]     : 0.f;
        float ss2 = (l < 8) ? red[l + 8] : 0.f;
#pragma unroll
        for (int o = 4; o; o >>= 1) {
            s2  += __shfl_xor_sync(0xffffffffu, s2,  o);
            ss2 += __shfl_xor_sync(0xffffffffu, ss2, o);
        }
        if (l == 0) { red[16] = s2; red[17] = ss2; }
    }
    __syncthreads();
    float mean = red[16] * (1.f / 1024.f);
    float var  = (red[17] - 1024.f * mean * mean) * (1.f / 1023.f);
    var = fmaxf(var, 0.f);
    float inv = 1.f / (sqrtf(var) + 1e-6f);
#pragma unroll
    for (int i = 0; i < 4; i++) {
        int c = t + i * 256;
        float r = alpha[c] * (v[i] - mean) * inv + bias[c];
        yr[c] = yg ? f2tff(r) : r;    // round when feeding a GEMM
    }
}

// ---------------- tf32 tensor-core SGEMM ------------------------------------
// C[M,N] = A[M,K] @ W[N,K]^T + bias. Operands pre-rounded. 3-stage cp.async.
// qkv_mode: blockIdx.x in [0,24): w = x>>3 selects WQ/WK/WV, col = (x&7)*128.
#define BM 128
#define BN 128
#define BK 32
#define TSTRIDE 36
#define TILE_FLTS ((BM + BN) * TSTRIDE)
#define NSTAGE 3
#define GEMM_SMEM (NSTAGE * TILE_FLTS * 4)

__global__ void __launch_bounds__(256)
gemm_kernel(int qkv_mode,
            const float* __restrict__ bias0,
            const float* __restrict__ bias1,
            const float* __restrict__ bias2)
{
    extern __shared__ float sh[];

    int w_sel, colBase;
    const float* A;
    const float* bias;
    float* C;
    int remap;
    if (qkv_mode) {
        w_sel   = blockIdx.x >> 3;
        colBase = (blockIdx.x & 7) * BN;
        A    = g_xn;
        bias = (w_sel == 0) ? bias0 : (w_sel == 1) ? bias1 : bias2;
        C    = (w_sel == 0) ? g_q : (w_sel == 1) ? g_k : g_v;
        remap = 1;
    } else {
        w_sel   = 3;
        colBase = blockIdx.x * BN;
        A    = g_ao;
        bias = bias0;
        C    = g_o;
        remap = 0;
    }
    const float* W = g_wr + (size_t)w_sel * KDIM * NDIM;

    const int tid = threadIdx.x;
    const int rowBase = blockIdx.y * BM;

    const int wid  = tid >> 5, lane = tid & 31;
    const int wm   = wid & 1,  wn   = wid >> 1;
    const int m0   = wm * 64,  n0   = wn * 32;
    const int lr   = lane >> 2, lc  = lane & 3;

    const float* Ab = A + (size_t)rowBase * KDIM;
    const float* Wb = W + (size_t)colBase * KDIM;

    float acc[4][4][4];
#pragma unroll
    for (int i = 0; i < 4; i++)
#pragma unroll
        for (int j = 0; j < 4; j++)
#pragma unroll
            for (int q = 0; q < 4; q++) acc[i][j][q] = 0.f;

    auto loadTile = [&](int kt) {
        float* sA = sh + (kt % NSTAGE) * TILE_FLTS;
        float* sW = sA + BM * TSTRIDE;
        const float* Asrc = Ab + kt * BK;
        const float* Wsrc = Wb + kt * BK;
#pragma unroll
        for (int i = 0; i < 4; i++) {
            int j = tid + i * 256;
            int r = j >> 3;
            int c = (j & 7) * 4;
            cp16(sA + r * TSTRIDE + c, Asrc + (size_t)r * KDIM + c);
        }
#pragma unroll
        for (int i = 0; i < 4; i++) {
            int j = tid + i * 256;
            int r = j >> 3;
            int c = (j & 7) * 4;
            cp16(sW + r * TSTRIDE + c, Wsrc + (size_t)r * KDIM + c);
        }
        asm volatile("cp.async.commit_group;\n");
    };

    const int NK = KDIM / BK;   // 32
    loadTile(0);
    loadTile(1);

    for (int kt = 0; kt < NK; kt++) {
        asm volatile("cp.async.wait_group 1;\n");
        __syncthreads();
        if (kt + 2 < NK) loadTile(kt + 2);

        const float* sA = sh + (kt % NSTAGE) * TILE_FLTS;
        const float* sW = sA + BM * TSTRIDE;

#pragma unroll
        for (int k8 = 0; k8 < BK / 8; k8++) {
            const int kc = k8 * 8 + lc;
            uint32_t a[4][4], b[4][2];
#pragma unroll
            for (int mi = 0; mi < 4; mi++) {
                const float* p = sA + (m0 + 16 * mi + lr) * TSTRIDE + kc;
                a[mi][0] = __float_as_uint(p[0]);
                a[mi][1] = __float_as_uint(p[8 * TSTRIDE]);
                a[mi][2] = __float_as_uint(p[4]);
                a[mi][3] = __float_as_uint(p[8 * TSTRIDE + 4]);
            }
#pragma unroll
            for (int ni = 0; ni < 4; ni++) {
                const float* p = sW + (n0 + 8 * ni + lr) * TSTRIDE + kc;
                b[ni][0] = __float_as_uint(p[0]);
                b[ni][1] = __float_as_uint(p[4]);
            }
#pragma unroll
            for (int mi = 0; mi < 4; mi++)
#pragma unroll
                for (int ni = 0; ni < 4; ni++)
                    mma_tf32(acc[mi][ni], a[mi], b[ni]);
        }
        __syncthreads();
    }

#pragma unroll
    for (int mi = 0; mi < 4; mi++) {
#pragma unroll
        for (int ni = 0; ni < 4; ni++) {
            int row0 = rowBase + m0 + 16 * mi + lr;
            int col0 = colBase + n0 + 8 * ni + 2 * lc;
            float b0 = bias[col0], b1 = bias[col0 + 1];
            float v00 = acc[mi][ni][0] + b0;
            float v01 = acc[mi][ni][1] + b1;
            float v10 = acc[mi][ni][2] + b0;
            float v11 = acc[mi][ni][3] + b1;
            if (remap) {
                // Q/K/V are consumed by tf32 MMA in attention: round now.
                v00 = f2tff(v00); v01 = f2tff(v01);
                v10 = f2tff(v10); v11 = f2tff(v11);
                int bidx = row0 >> 9, e = row0 & 511;
                int hh = col0 >> 6,  d = col0 & 63;
                size_t base0 = (((size_t)(bidx * 16 + hh) * 512) + e) * 64 + d;
                C[base0]     = v00;
                C[base0 + 1] = v01;
                size_t base1 = base0 + (size_t)8 * 64;
                C[base1]     = v10;
                C[base1 + 1] = v11;
            } else {
                C[(size_t)row0 * NDIM + col0]           = v00;
                C[(size_t)row0 * NDIM + col0 + 1]       = v01;
                C[(size_t)(row0 + 8) * NDIM + col0]     = v10;
                C[(size_t)(row0 + 8) * NDIM + col0 + 1] = v11;
            }
        }
    }
}

// ---------------- attention (tensor-core) ------------------------------------
// Per (b,h,32-q-tile): S = (Q/8)@K^T via tf32 MMA, masked softmax over 512,
// write e (streaming), O^T = V^T @ E^T via tf32 MMA. 256 threads, 2 CTAs/SM.
#define QT  32
#define KC  128
#define SST 520     // 520 % 32 == 8  -> conflict-free E-fragment reads
#define QS  68      // 68  % 32 == 4  -> conflict-free Q/K fragment reads
#define VS  72      // 72  % 32 == 8  -> conflict-free V^T fragment reads
#define ATTN_SMEM ((QT * QS + KC * VS + QT * SST + 32) * 4)

__global__ void __launch_bounds__(256, 2)
attn_kernel(float* __restrict__ e_out)
{
    extern __shared__ float sh[];
    float* sQ   = sh;                 // 32 x QS   (reused as sO)
    float* sKV  = sQ + QT * QS;       // 128 x VS buffer (K uses stride QS, V uses VS)
    float* sS   = sKV + KC * VS;      // 32 x SST
    float* sInv = sS + QT * SST;      // 32

    const int qt = blockIdx.x, h = blockIdx.y, b = blockIdx.z;
    const int tid = threadIdx.x;
    const int lane = tid & 31, wid = tid >> 5;
    const int lr = lane >> 2, lc = lane & 3;
    const int q0 = qt * QT;

    const float* Q  = g_q + (size_t)(b * 16 + h) * 512 * 64;
    const float* Kp = g_k + (size_t)(b * 16 + h) * 512 * 64;
    const float* Vp = g_v + (size_t)(b * 16 + h) * 512 * 64;

    // ---- load Q tile scaled by 1/8 (power of 2: stays tf32-exact) ----
#pragma unroll
    for (int i = 0; i < 2; i++) {
        int f = tid + i * 256;
        int r = f >> 4;
        int c = (f & 15) * 4;
        float4 v = *(const float4*)(Q + (size_t)(q0 + r) * 64 + c);
        v.x *= 0.125f; v.y *= 0.125f; v.z *= 0.125f; v.w *= 0.125f;
        *(float4*)&sQ[r * QS + c] = v;
    }

    // ---- scores: S[32,512] ----
    const int wm = wid & 1, wn = wid >> 1;   // 2 x 4 warp grid
    for (int kb = 0; kb < 512; kb += KC) {
        __syncthreads();
#pragma unroll
        for (int i = 0; i < 8; i++) {
            int f = tid + i * 256;
            int r = f >> 4;
            int c = (f & 15) * 4;
            cp16(sKV + r * QS + c, Kp + (size_t)(kb + r) * 64 + c);
        }
        asm volatile("cp.async.commit_group;\n");
        asm volatile("cp.async.wait_group 0;\n");
        __syncthreads();

        float acc[4][4] = {};
#pragma unroll
        for (int k8 = 0; k8 < 8; k8++) {
            const int kc = k8 * 8 + lc;
            uint32_t a[4], bfr[4][2];
            const float* p = sQ + (wm * 16 + lr) * QS + kc;
            a[0] = __float_as_uint(p[0]);
            a[1] = __float_as_uint(p[8 * QS]);
            a[2] = __float_as_uint(p[4]);
            a[3] = __float_as_uint(p[8 * QS + 4]);
#pragma unroll
            for (int ni = 0; ni < 4; ni++) {
                const float* pk = sKV + (wn * 32 + ni * 8 + lr) * QS + kc;
                bfr[ni][0] = __float_as_uint(pk[0]);
                bfr[ni][1] = __float_as_uint(pk[4]);
            }
#pragma unroll
            for (int ni = 0; ni < 4; ni++)
                mma_tf32(acc[ni], a, bfr[ni]);
        }
        const int row = wm * 16 + lr;
#pragma unroll
        for (int ni = 0; ni < 4; ni++) {
            int col = kb + wn * 32 + ni * 8 + 2 * lc;
            sS[row * SST + col]             = acc[ni][0];
            sS[row * SST + col + 1]         = acc[ni][1];
            sS[(row + 8) * SST + col]       = acc[ni][2];
            sS[(row + 8) * SST + col + 1]   = acc[ni][3];
        }
    }
    __syncthreads();

    // ---- prefetch V chunk 0 into sKV (K data is dead now); overlaps softmax ----
#pragma unroll
    for (int i = 0; i < 8; i++) {
        int f = tid + i * 256;
        int r = f >> 4;
        int c = (f & 15) * 4;
        cp16(sKV + r * VS + c, Vp + (size_t)r * 64 + c);
    }
    asm volatile("cp.async.commit_group;\n");

    // ---- masked softmax (8 warps x 4 rows) ----
    const float NEGINF = __int_as_float(0xff800000);
    const unsigned char* mbase = g_mask8 + ((size_t)b * 512 + q0) * 512;
#pragma unroll
    for (int rr = 0; rr < 4; rr++) {
        int r = wid * 4 + rr;
        float* srow = sS + r * SST;
        const unsigned char* mr = mbase + (size_t)r * 512;
        unsigned int mbits = 0;
        float mx = NEGINF;
#pragma unroll
        for (int i = 0; i < 16; i++) {
            int k = lane + 32 * i;
            if (mr[k]) mbits |= (1u << i);
            else       mx = fmaxf(mx, srow[k]);
        }
#pragma unroll
        for (int o = 16; o; o >>= 1) mx = fmaxf(mx, __shfl_xor_sync(0xffffffffu, mx, o));
        float sum = 0.f;
#pragma unroll
        for (int i = 0; i < 16; i++) {
            int k = lane + 32 * i;
            float ev = (mbits >> i) & 1 ? 0.f : __expf(srow[k] - mx);
            srow[k] = ev;
            sum += ev;
        }
#pragma unroll
        for (int o = 16; o; o >>= 1) sum += __shfl_xor_sync(0xffffffffu, sum, o);
        if (lane == 0) sInv[r] = 1.f / sum;
    }
    __syncthreads();

    // ---- write e (normalized), coalesced float4, streaming ----
    float* erow = e_out + (((size_t)(b * 16 + h) * 512) + q0) * 512;
#pragma unroll
    for (int i = 0; i < 16; i++) {
        int idx = tid + i * 256;
        int r = idx >> 7;
        int c = (idx & 127) * 4;
        float inv = sInv[r];
        float4 v = *(const float4*)&sS[r * SST + c];
        v.x *= inv; v.y *= inv; v.z *= inv; v.w *= inv;
        __stcs((float4*)(erow + (size_t)r * 512 + c), v);
    }

    // ---- O^T = V^T @ E^T ----
    const int wd = wid & 3, wq = wid >> 2;   // 4 d-blocks x 2 q-halves
    const int d0 = wd * 16, qb = wq * 16;
    float oacc[2][4] = {};
    for (int kb = 0; kb < 512; kb += KC) {
        if (kb) {
            __syncthreads();
#pragma unroll
            for (int i = 0; i < 8; i++) {
                int f = tid + i * 256;
                int r = f >> 4;
                int c = (f & 15) * 4;
                cp16(sKV + r * VS + c, Vp + (size_t)(kb + r) * 64 + c);
            }
            asm volatile("cp.async.commit_group;\n");
        }
        asm volatile("cp.async.wait_group 0;\n");
        __syncthreads();

#pragma unroll
        for (int k8 = 0; k8 < KC / 8; k8++) {
            const int kc = k8 * 8 + lc;
            uint32_t a[4], bfr[2][2];
            const float* pv = sKV + kc * VS + d0 + lr;
            a[0] = __float_as_uint(pv[0]);
            a[1] = __float_as_uint(pv[8]);
            a[2] = __float_as_uint(pv[4 * VS]);
            a[3] = __float_as_uint(pv[4 * VS + 8]);
#pragma unroll
            for (int ni = 0; ni < 2; ni++) {
                const float* pe = sS + (qb + ni * 8 + lr) * SST + kb + kc;
                bfr[ni][0] = f2tf(pe[0]);
                bfr[ni][1] = f2tf(pe[4]);
            }
#pragma unroll
            for (int ni = 0; ni < 2; ni++)
                mma_tf32(oacc[ni], a, bfr[ni]);
        }
    }
    __syncthreads();

    // ---- normalize, stage O[q][d] in smem (reuse sQ), write coalesced ----
    float* sO = sQ;
#pragma unroll
    for (int ni = 0; ni < 2; ni++) {
        int q = qb + ni * 8 + 2 * lc;
        float i0 = sInv[q], i1 = sInv[q + 1];
        sO[q * QS + d0 + lr]           = oacc[ni][0] * i0;
        sO[(q + 1) * QS + d0 + lr]     = oacc[ni][1] * i1;
        sO[q * QS + d0 + lr + 8]       = oacc[ni][2] * i0;
        sO[(q + 1) * QS + d0 + lr + 8] = oacc[ni][3] * i1;
    }
    __syncthreads();
#pragma unroll
    for (int i = 0; i < 2; i++) {
        int f = tid + i * 256;
        int r = f >> 4;
        int c = (f & 15) * 4;
        float4 v = *(const float4*)&sO[r * QS + c];
        v.x = f2tff(v.x); v.y = f2tff(v.y); v.z = f2tff(v.z); v.w = f2tff(v.w);
        *(float4*)(g_ao + ((size_t)(b * 512 + q0 + r)) * 1024 + h * 64 + c) = v;
    }
}

// ---------------- launch ------------------------------------------------------
extern "C" void kernel_launch(void* const* d_in, const int* in_sizes, int n_in,
                              void* d_out, int out_size)
{
    const float*         events = (const float*)d_in[0];
    const unsigned char* mask   = (const unsigned char*)d_in[1];
    const float*         n1a    = (const float*)d_in[2];
    const float*         n1b    = (const float*)d_in[3];
    const float*         wq     = (const float*)d_in[4];
    const float*         bq     = (const float*)d_in[5];
    const float*         wk     = (const float*)d_in[6];
    const float*         bk     = (const float*)d_in[7];
    const float*         wv     = (const float*)d_in[8];
    const float*         bv     = (const float*)d_in[9];
    const float*         wo     = (const float*)d_in[10];
    const float*         bo     = (const float*)d_in[11];
    const float*         n2a    = (const float*)d_in[12];
    const float*         n2b    = (const float*)d_in[13];

    float* out   = (float*)d_out;                       // [16,512,1024]
    float* e_out = out + (size_t)MROWS * 1024;          // [16,16,512,512]

    mask_detect_kernel<<<1, 256>>>(mask);
    mask_convert_kernel<<<4096, 256>>>(mask);
    round_kernel<<<4096, 256>>>(wq, wk, wv, wo);

    norm_kernel<<<MROWS, 256>>>(events, n1a, n1b, nullptr, 0, 1);

    cudaFuncSetAttribute(gemm_kernel,
                         cudaFuncAttributeMaxDynamicSharedMemorySize, GEMM_SMEM);
    // fused QKV: grid (24, 64)
    gemm_kernel<<<dim3(24, MROWS / BM), 256, GEMM_SMEM>>>(1, bq, bk, bv);

    cudaFuncSetAttribute(attn_kernel,
                         cudaFuncAttributeMaxDynamicSharedMemorySize, ATTN_SMEM);
    attn_kernel<<<dim3(16, 16, 16), 256, ATTN_SMEM>>>(e_out);

    gemm_kernel<<<dim3(8, MROWS / BM), 256, GEMM_SMEM>>>(0, bo, nullptr, nullptr);

    norm_kernel<<<MROWS, 256>>>(nullptr, n2a, n2b, out, 1, 0);
}

// round 6
// speedup vs baseline: 5.9868x; 1.6138x over previous
#include <cuda_runtime.h>
#include <cuda_fp16.h>
#include <cstdint>

// Problem constants
#define B_   16
#define NE_  512
#define NIN_ 1024
#define H_   16
#define HD_  64
#define MROWS 8192           // B_*NE_
#define KDIM 1024
#define NDIM 1024

// ---------------- scratch (device globals; no allocations allowed) ----------
__device__ __half g_xn[(size_t)MROWS * NIN_];
__device__ __half g_q [(size_t)MROWS * NIN_];   // [B,H,NE,HD]
__device__ __half g_k [(size_t)MROWS * NIN_];
__device__ __half g_v [(size_t)MROWS * NIN_];
__device__ __half g_ao[(size_t)MROWS * NIN_];   // attention output [M,1024]
__device__ float  g_o [(size_t)MROWS * NIN_];   // WO output, pre-norm2 (f32)
__device__ __half g_wr[(size_t)4 * KDIM * NDIM];// fp16 weights (WQ,WK,WV,WO)
__device__ unsigned char g_mask8[(size_t)B_ * NE_ * NE_];
__device__ int   g_mask_kind;                   // 0=u8/bool, 1=int32, 2=float32

// ---------------- helpers ----------------------------------------------------
__device__ __forceinline__ void cp16(void* dst, const void* src)
{
    uint32_t d = (uint32_t)__cvta_generic_to_shared(dst);
    asm volatile("cp.async.cg.shared.global [%0], [%1], 16;\n" :: "r"(d), "l"(src));
}
__device__ __forceinline__ uint32_t smem_u32(const void* p)
{
    uint32_t a;
    asm("{ .reg .u64 t; cvta.to.shared.u64 t, %1; cvt.u32.u64 %0, t; }"
        : "=r"(a) : "l"(p));
    return a;
}
__device__ __forceinline__ void ldm_x4(uint32_t* r, uint32_t addr)
{
    asm volatile("ldmatrix.sync.aligned.m8n8.x4.shared.b16 {%0,%1,%2,%3}, [%4];"
                 : "=r"(r[0]), "=r"(r[1]), "=r"(r[2]), "=r"(r[3]) : "r"(addr));
}
__device__ __forceinline__ void ldm_x4t(uint32_t* r, uint32_t addr)
{
    asm volatile("ldmatrix.sync.aligned.m8n8.x4.trans.shared.b16 {%0,%1,%2,%3}, [%4];"
                 : "=r"(r[0]), "=r"(r[1]), "=r"(r[2]), "=r"(r[3]) : "r"(addr));
}
__device__ __forceinline__ void mma_f16(float* c, const uint32_t* a,
                                        uint32_t b0, uint32_t b1)
{
    asm volatile(
        "mma.sync.aligned.m16n8k16.row.col.f32.f16.f16.f32 "
        "{%0,%1,%2,%3}, {%4,%5,%6,%7}, {%8,%9}, {%0,%1,%2,%3};"
        : "+f"(c[0]), "+f"(c[1]), "+f"(c[2]), "+f"(c[3])
        : "r"(a[0]), "r"(a[1]), "r"(a[2]), "r"(a[3]), "r"(b0), "r"(b1));
}

// ---------------- mask dtype detector ---------------------------------------
__global__ void mask_detect_kernel(const unsigned char* __restrict__ m)
{
    __shared__ int c1s, c2s;
    if (threadIdx.x == 0) { c1s = 0; c2s = 0; }
    __syncthreads();
    int c1 = 0, c2 = 0;
    for (int i = threadIdx.x; i < 16384; i += 256) {
        unsigned char v = m[i];
        int r = i & 3;
        if (v && r != 0) c1++;
        if (v && r <= 1) c2++;
    }
    atomicAdd(&c1s, c1);
    atomicAdd(&c2s, c2);
    __syncthreads();
    if (threadIdx.x == 0)
        g_mask_kind = (c1s == 0) ? 1 : ((c2s == 0) ? 2 : 0);
}

// ---------------- mask -> u8 convert -----------------------------------------
__global__ void mask_convert_kernel(const unsigned char* __restrict__ m)
{
    int kind = g_mask_kind;
    size_t i = ((size_t)blockIdx.x * 256 + threadIdx.x) * 4;
    uchar4 o;
    if (kind == 1) {
        int4 v = *(const int4*)((const int*)m + i);
        o.x = v.x != 0; o.y = v.y != 0; o.z = v.z != 0; o.w = v.w != 0;
    } else if (kind == 2) {
        float4 v = *(const float4*)((const float*)m + i);
        o.x = v.x != 0.f; o.y = v.y != 0.f; o.z = v.z != 0.f; o.w = v.w != 0.f;
    } else {
        uchar4 v = *(const uchar4*)(m + i);
        o.x = v.x != 0; o.y = v.y != 0; o.z = v.z != 0; o.w = v.w != 0;
    }
    *(uchar4*)(g_mask8 + i) = o;
}

// ---------------- weight f32 -> fp16 (all 4 in one launch) --------------------
__global__ void round_kernel(const float* __restrict__ s0, const float* __restrict__ s1,
                             const float* __restrict__ s2, const float* __restrict__ s3)
{
    int sel = blockIdx.x >> 9;
    const float* src = sel == 0 ? s0 : sel == 1 ? s1 : sel == 2 ? s2 : s3;
    size_t i = (((size_t)(blockIdx.x & 511) * 256) + threadIdx.x) * 8;
    __half* dst = g_wr + (size_t)sel * KDIM * NDIM;
    float4 v0 = *(const float4*)(src + i);
    float4 v1 = *(const float4*)(src + i + 4);
    __half2 h[4];
    h[0] = __floats2half2_rn(v0.x, v0.y);
    h[1] = __floats2half2_rn(v0.z, v0.w);
    h[2] = __floats2half2_rn(v1.x, v1.y);
    h[3] = __floats2half2_rn(v1.z, v1.w);
    *(uint4*)(dst + i) = *(const uint4*)h;
}

// ---------------- layernorm (PyTorch-style: unbiased std, /(std+eps)) -------
__global__ void norm_kernel(const float* __restrict__ xin,
                            const float* __restrict__ alpha,
                            const float* __restrict__ bias,
                            float* __restrict__ yout,
                            int xg, int yg)
{
    const float* x = xg ? g_o : xin;
    int row = blockIdx.x;
    const float* xr = x + (size_t)row * 1024;
    int t = threadIdx.x;

    float v[4];
    float s = 0.f, ss = 0.f;
#pragma unroll
    for (int i = 0; i < 4; i++) {
        v[i] = xr[t + i * 256];
        s += v[i];
        ss += v[i] * v[i];
    }
#pragma unroll
    for (int o = 16; o; o >>= 1) {
        s  += __shfl_xor_sync(0xffffffffu, s,  o);
        ss += __shfl_xor_sync(0xffffffffu, ss, o);
    }
    __shared__ float red[32];
    int w = t >> 5, l = t & 31;
    if (l == 0) { red[w] = s; red[w + 8] = ss; }
    __syncthreads();
    if (w == 0) {
        float s2  = (l < 8) ? red[l]     : 0.f;
        float ss2 = (l < 8) ? red[l + 8] : 0.f;
#pragma unroll
        for (int o = 4; o; o >>= 1) {
            s2  += __shfl_xor_sync(0xffffffffu, s2,  o);
            ss2 += __shfl_xor_sync(0xffffffffu, ss2, o);
        }
        if (l == 0) { red[16] = s2; red[17] = ss2; }
    }
    __syncthreads();
    float mean = red[16] * (1.f / 1024.f);
    float var  = (red[17] - 1024.f * mean * mean) * (1.f / 1023.f);
    var = fmaxf(var, 0.f);
    float inv = 1.f / (sqrtf(var) + 1e-6f);
    if (yg) {
        __half* yr = g_xn + (size_t)row * 1024;
#pragma unroll
        for (int i = 0; i < 4; i++) {
            int c = t + i * 256;
            yr[c] = __float2half_rn(alpha[c] * (v[i] - mean) * inv + bias[c]);
        }
    } else {
        float* yr = yout + (size_t)row * 1024;
#pragma unroll
        for (int i = 0; i < 4; i++) {
            int c = t + i * 256;
            yr[c] = alpha[c] * (v[i] - mean) * inv + bias[c];
        }
    }
}

// ---------------- fp16 tensor-core GEMM --------------------------------------
// C[M,N] = A[M,K] @ W[N,K]^T + bias. BM=128, BN=128, BK=64, 3-stage cp.async,
// 8 warps x (64x32) tiles via m16n8k16 fp16 MMA + ldmatrix.
#define GA_STRIDE 144                 // bytes per 64-half row (72 halfs)
#define GA_TILE   (128 * GA_STRIDE)   // 18432 B
#define G_STAGE   (2 * GA_TILE)       // A+B per stage
#define GEMM_SMEM (3 * G_STAGE)       // 110592 B

__global__ void __launch_bounds__(256, 2)
gemm_kernel(int qkv_mode,
            const float* __restrict__ bias0,
            const float* __restrict__ bias1,
            const float* __restrict__ bias2)
{
    extern __shared__ char sh[];
    const uint32_t shb = smem_u32(sh);

    int w_sel, colBase;
    const __half* A;
    const float* bias;
    __half* Ch = nullptr;
    float* Cf = nullptr;
    int remap;
    if (qkv_mode) {
        w_sel   = blockIdx.x >> 3;
        colBase = (blockIdx.x & 7) * 128;
        A    = g_xn;
        bias = (w_sel == 0) ? bias0 : (w_sel == 1) ? bias1 : bias2;
        Ch   = (w_sel == 0) ? g_q : (w_sel == 1) ? g_k : g_v;
        remap = 1;
    } else {
        w_sel   = 3;
        colBase = blockIdx.x * 128;
        A    = g_ao;
        bias = bias0;
        Cf   = g_o;
        remap = 0;
    }
    const __half* W = g_wr + (size_t)w_sel * KDIM * NDIM;

    const int tid = threadIdx.x;
    const int wid = tid >> 5, lane = tid & 31;
    const int wm = wid & 1, wn = wid >> 1;
    const int m0 = wm * 64, n0 = wn * 32;
    const int lr = lane >> 2, lc = lane & 3;
    const int rowBase = blockIdx.y * 128;

    const __half* Ab = A + (size_t)rowBase * KDIM;
    const __half* Wb = W + (size_t)colBase * KDIM;

    float acc[4][4][4];
#pragma unroll
    for (int i = 0; i < 4; i++)
#pragma unroll
        for (int j = 0; j < 4; j++)
#pragma unroll
            for (int q = 0; q < 4; q++) acc[i][j][q] = 0.f;

    auto loadChunk = [&](int kt) {
        char* sA = sh + (kt % 3) * G_STAGE;
        char* sB = sA + GA_TILE;
#pragma unroll
        for (int i = 0; i < 4; i++) {
            int g = tid + i * 256;          // 0..1023
            int r = g >> 3, c = g & 7;      // row, 16B granule
            cp16(sA + r * GA_STRIDE + c * 16, Ab + (size_t)r * KDIM + kt * 64 + c * 8);
        }
#pragma unroll
        for (int i = 0; i < 4; i++) {
            int g = tid + i * 256;
            int r = g >> 3, c = g & 7;
            cp16(sB + r * GA_STRIDE + c * 16, Wb + (size_t)r * KDIM + kt * 64 + c * 8);
        }
        asm volatile("cp.async.commit_group;\n");
    };

    const int NK = KDIM / 64;   // 16
    loadChunk(0);
    loadChunk(1);

    // ldmatrix lane addressing offsets
    const int aRow = lane & 15, aColH = (lane >> 4) << 3;              // A frags
    const int bRow = ((lane >> 4) << 3) + (lane & 7);                  // B frags
    const int bColH = ((lane >> 3) & 1) << 3;

    for (int kt = 0; kt < NK; kt++) {
        if (kt + 1 < NK) { asm volatile("cp.async.wait_group 1;\n"); }
        else             { asm volatile("cp.async.wait_group 0;\n"); }
        __syncthreads();
        if (kt + 2 < NK) loadChunk(kt + 2);

        const uint32_t sAb = shb + (kt % 3) * G_STAGE;
        const uint32_t sBb = sAb + GA_TILE;

#pragma unroll
        for (int k16 = 0; k16 < 4; k16++) {
            uint32_t a[4][4], b[2][4];
#pragma unroll
            for (int mi = 0; mi < 4; mi++)
                ldm_x4(a[mi], sAb + (m0 + 16 * mi + aRow) * GA_STRIDE +
                              (k16 * 16 + aColH) * 2);
#pragma unroll
            for (int ni2 = 0; ni2 < 2; ni2++)
                ldm_x4(b[ni2], sBb + (n0 + ni2 * 16 + bRow) * GA_STRIDE +
                               (k16 * 16 + bColH) * 2);
#pragma unroll
            for (int mi = 0; mi < 4; mi++)
#pragma unroll
                for (int ni = 0; ni < 4; ni++)
                    mma_f16(acc[mi][ni], a[mi],
                            b[ni >> 1][(ni & 1) * 2], b[ni >> 1][(ni & 1) * 2 + 1]);
        }
        __syncthreads();
    }

#pragma unroll
    for (int mi = 0; mi < 4; mi++) {
#pragma unroll
        for (int ni = 0; ni < 4; ni++) {
            int row0 = rowBase + m0 + 16 * mi + lr;
            int col0 = colBase + n0 + 8 * ni + 2 * lc;
            float b0 = bias[col0], b1 = bias[col0 + 1];
            float v00 = acc[mi][ni][0] + b0;
            float v01 = acc[mi][ni][1] + b1;
            float v10 = acc[mi][ni][2] + b0;
            float v11 = acc[mi][ni][3] + b1;
            if (remap) {
                int bidx = row0 >> 9, e = row0 & 511;
                int hh = col0 >> 6,  d = col0 & 63;
                size_t base0 = (((size_t)(bidx * 16 + hh) * 512) + e) * 64 + d;
                *(__half2*)&Ch[base0]              = __floats2half2_rn(v00, v01);
                *(__half2*)&Ch[base0 + (size_t)512]= __floats2half2_rn(v10, v11);
            } else {
                *(float2*)&Cf[(size_t)row0 * NDIM + col0]       = make_float2(v00, v01);
                *(float2*)&Cf[(size_t)(row0 + 8) * NDIM + col0] = make_float2(v10, v11);
            }
        }
    }
}

// ---------------- attention (fp16 tensor-core) --------------------------------
// Per (b,h,32-q-tile): S = (Q/8)@K^T, exact masked softmax (f32), write e (f32),
// in-place E->half, O^T = V^T @ E^T. 256 threads, 2 CTAs/SM.
#define A_STRIDE 144                  // bytes per 64-half row (Q/K/V tiles)
#define OFF_Q    0                    // 32 x 144B = 4608
#define OFF_KV   4608                 // 128 x 144B = 18432
#define OFF_S    23040                // 32 x 520 f32 = 66560
#define SST      520
#define OFF_INV  89600                // 32 f32
#define ATTN_SMEM 89728

__global__ void __launch_bounds__(256, 2)
attn_kernel(float* __restrict__ e_out)
{
    extern __shared__ char sh[];
    const uint32_t shb = smem_u32(sh);
    __half* sQ   = (__half*)(sh + OFF_Q);
    __half* sKV  = (__half*)(sh + OFF_KV);
    float*  sS   = (float*)(sh + OFF_S);
    float*  sInv = (float*)(sh + OFF_INV);

    const int qt = blockIdx.x, h = blockIdx.y, b = blockIdx.z;
    const int tid = threadIdx.x;
    const int lane = tid & 31, wid = tid >> 5;
    const int lr = lane >> 2, lc = lane & 3;
    const int q0 = qt * 32;

    const __half* Q  = g_q + (size_t)(b * 16 + h) * 512 * 64;
    const __half* Kp = g_k + (size_t)(b * 16 + h) * 512 * 64;
    const __half* Vp = g_v + (size_t)(b * 16 + h) * 512 * 64;

    // ---- load Q tile scaled by 1/8 (exact in fp16) ----
    {
        const __half2 sc = __half2half2(__float2half(0.125f));
        int r = tid >> 3, c8 = tid & 7;
        uint4 raw = *(const uint4*)(Q + (size_t)(q0 + r) * 64 + c8 * 8);
        __half2* hp = (__half2*)&raw;
#pragma unroll
        for (int j = 0; j < 4; j++) hp[j] = __hmul2(hp[j], sc);
        *(uint4*)((char*)sQ + r * A_STRIDE + c8 * 16) = raw;
    }

    const int aRow = lane & 15, aColH = (lane >> 4) << 3;
    const int bRow = ((lane >> 4) << 3) + (lane & 7);
    const int bColH = ((lane >> 3) & 1) << 3;

    // ---- scores: S[32,512] ----
    const int wm = wid & 1, wn = wid >> 1;
    for (int kb = 0; kb < 512; kb += 128) {
        __syncthreads();
#pragma unroll
        for (int i = 0; i < 4; i++) {
            int g = tid + i * 256;
            int r = g >> 3, c = g & 7;
            cp16((char*)sKV + r * A_STRIDE + c * 16,
                 Kp + (size_t)(kb + r) * 64 + c * 8);
        }
        asm volatile("cp.async.commit_group;\n");
        asm volatile("cp.async.wait_group 0;\n");
        __syncthreads();

        float acc[4][4] = {};
#pragma unroll
        for (int k16 = 0; k16 < 4; k16++) {
            uint32_t a[4], bf[2][4];
            ldm_x4(a, shb + OFF_Q + (wm * 16 + aRow) * A_STRIDE +
                      (k16 * 16 + aColH) * 2);
#pragma unroll
            for (int ni2 = 0; ni2 < 2; ni2++)
                ldm_x4(bf[ni2], shb + OFF_KV +
                       (wn * 32 + ni2 * 16 + bRow) * A_STRIDE +
                       (k16 * 16 + bColH) * 2);
#pragma unroll
            for (int ni = 0; ni < 4; ni++)
                mma_f16(acc[ni], a, bf[ni >> 1][(ni & 1) * 2],
                        bf[ni >> 1][(ni & 1) * 2 + 1]);
        }
        const int row = wm * 16 + lr;
#pragma unroll
        for (int ni = 0; ni < 4; ni++) {
            int col = kb + wn * 32 + ni * 8 + 2 * lc;
            sS[row * SST + col]           = acc[ni][0];
            sS[row * SST + col + 1]       = acc[ni][1];
            sS[(row + 8) * SST + col]     = acc[ni][2];
            sS[(row + 8) * SST + col + 1] = acc[ni][3];
        }
    }
    __syncthreads();

    // ---- prefetch V chunk 0 (K data dead); overlaps softmax ----
#pragma unroll
    for (int i = 0; i < 4; i++) {
        int g = tid + i * 256;
        int r = g >> 3, c = g & 7;
        cp16((char*)sKV + r * A_STRIDE + c * 16, Vp + (size_t)r * 64 + c * 8);
    }
    asm volatile("cp.async.commit_group;\n");

    // ---- masked softmax (8 warps x 4 rows), exact f32 ----
    const float NEGINF = __int_as_float(0xff800000);
    const unsigned char* mbase = g_mask8 + ((size_t)b * 512 + q0) * 512;
#pragma unroll
    for (int rr = 0; rr < 4; rr++) {
        int r = wid * 4 + rr;
        float* srow = sS + r * SST;
        const unsigned char* mr = mbase + (size_t)r * 512;
        unsigned int mbits = 0;
        float mx = NEGINF;
#pragma unroll
        for (int i = 0; i < 16; i++) {
            int k = lane + 32 * i;
            if (mr[k]) mbits |= (1u << i);
            else       mx = fmaxf(mx, srow[k]);
        }
#pragma unroll
        for (int o = 16; o; o >>= 1) mx = fmaxf(mx, __shfl_xor_sync(0xffffffffu, mx, o));
        float sum = 0.f;
#pragma unroll
        for (int i = 0; i < 16; i++) {
            int k = lane + 32 * i;
            float ev = (mbits >> i) & 1 ? 0.f : __expf(srow[k] - mx);
            srow[k] = ev;
            sum += ev;
        }
#pragma unroll
        for (int o = 16; o; o >>= 1) sum += __shfl_xor_sync(0xffffffffu, sum, o);
        if (lane == 0) sInv[r] = 1.f / sum;
    }
    __syncthreads();

    // ---- write e (normalized f32), coalesced, streaming ----
    float* erow = e_out + (((size_t)(b * 16 + h) * 512) + q0) * 512;
#pragma unroll
    for (int i = 0; i < 16; i++) {
        int idx = tid + i * 256;
        int r = idx >> 7;
        int c = (idx & 127) * 4;
        float inv = sInv[r];
        float4 v = *(const float4*)&sS[r * SST + c];
        v.x *= inv; v.y *= inv; v.z *= inv; v.w *= inv;
        __stcs((float4*)(erow + (size_t)r * 512 + c), v);
    }
    __syncthreads();

    // ---- in-place E f32 -> half (4 stages of 8 rows, race-free) ----
    {
        char* Ec = (char*)sS;
#pragma unroll
        for (int s = 0; s < 4; s++) {
            int r = 8 * s + (tid >> 5);
            int k = lane * 16;
            float4 f[4];
#pragma unroll
            for (int j = 0; j < 4; j++)
                f[j] = *(const float4*)&sS[r * SST + k + 4 * j];
            __syncthreads();
            __half2 hbuf[8];
#pragma unroll
            for (int j = 0; j < 4; j++) {
                hbuf[2 * j]     = __floats2half2_rn(f[j].x, f[j].y);
                hbuf[2 * j + 1] = __floats2half2_rn(f[j].z, f[j].w);
            }
            *(uint4*)(Ec + r * 2080 + k * 2)      = *(const uint4*)&hbuf[0];
            *(uint4*)(Ec + r * 2080 + k * 2 + 16) = *(const uint4*)&hbuf[4];
            __syncthreads();
        }
    }

    // ---- O^T = V^T @ E^T (fp16) ----
    const char* Ec = (const char*)sS;
    const int wd = wid & 3, wq = wid >> 2;
    const int d0 = wd * 16, qb = wq * 16;
    float oacc[2][4] = {};
    for (int kb = 0; kb < 512; kb += 128) {
        if (kb) {
            __syncthreads();
#pragma unroll
            for (int i = 0; i < 4; i++) {
                int g = tid + i * 256;
                int r = g >> 3, c = g & 7;
                cp16((char*)sKV + r * A_STRIDE + c * 16,
                     Vp + (size_t)(kb + r) * 64 + c * 8);
            }
            asm volatile("cp.async.commit_group;\n");
        }
        asm volatile("cp.async.wait_group 0;\n");
        __syncthreads();

#pragma unroll
        for (int k16 = 0; k16 < 8; k16++) {
            uint32_t a[4];
            // V^T fragment via trans ldmatrix: rows = kv, col = d
            ldm_x4t(a, shb + OFF_KV + (k16 * 16 + bRow) * A_STRIDE +
                       (d0 + bColH) * 2);
#pragma unroll
            for (int ni = 0; ni < 2; ni++) {
                int n = qb + ni * 8 + lr;
                const char* ep = Ec + n * 2080 + (kb + k16 * 16 + lc * 2) * 2;
                uint32_t b0 = *(const uint32_t*)ep;
                uint32_t b1 = *(const uint32_t*)(ep + 16);
                mma_f16(oacc[ni], a, b0, b1);
            }
        }
    }
    __syncthreads();

    // ---- normalize, stage O[q][d] as half in sQ region, write coalesced ----
    __half* sO = sQ;
#pragma unroll
    for (int ni = 0; ni < 2; ni++) {
        int q = qb + ni * 8 + 2 * lc;
        float i0 = sInv[q], i1 = sInv[q + 1];
        sO[q * 72 + d0 + lr]           = __float2half_rn(oacc[ni][0] * i0);
        sO[(q + 1) * 72 + d0 + lr]     = __float2half_rn(oacc[ni][1] * i1);
        sO[q * 72 + d0 + lr + 8]       = __float2half_rn(oacc[ni][2] * i0);
        sO[(q + 1) * 72 + d0 + lr + 8] = __float2half_rn(oacc[ni][3] * i1);
    }
    __syncthreads();
    {
        int r = tid >> 3, c = tid & 7;
        uint4 v = *(const uint4*)((const char*)sO + r * A_STRIDE + c * 16);
        *(uint4*)(g_ao + ((size_t)(b * 512 + q0 + r)) * 1024 + h * 64 + c * 8) = v;
    }
}

// ---------------- launch ------------------------------------------------------
extern "C" void kernel_launch(void* const* d_in, const int* in_sizes, int n_in,
                              void* d_out, int out_size)
{
    const float*         events = (const float*)d_in[0];
    const unsigned char* mask   = (const unsigned char*)d_in[1];
    const float*         n1a    = (const float*)d_in[2];
    const float*         n1b    = (const float*)d_in[3];
    const float*         wq     = (const float*)d_in[4];
    const float*         bq     = (const float*)d_in[5];
    const float*         wk     = (const float*)d_in[6];
    const float*         bk     = (const float*)d_in[7];
    const float*         wv     = (const float*)d_in[8];
    const float*         bv     = (const float*)d_in[9];
    const float*         wo     = (const float*)d_in[10];
    const float*         bo     = (const float*)d_in[11];
    const float*         n2a    = (const float*)d_in[12];
    const float*         n2b    = (const float*)d_in[13];

    float* out   = (float*)d_out;                       // [16,512,1024]
    float* e_out = out + (size_t)MROWS * 1024;          // [16,16,512,512]

    mask_detect_kernel<<<1, 256>>>(mask);
    mask_convert_kernel<<<4096, 256>>>(mask);
    round_kernel<<<2048, 256>>>(wq, wk, wv, wo);

    norm_kernel<<<MROWS, 256>>>(events, n1a, n1b, nullptr, 0, 1);

    cudaFuncSetAttribute(gemm_kernel,
                         cudaFuncAttributeMaxDynamicSharedMemorySize, GEMM_SMEM);
    gemm_kernel<<<dim3(24, MROWS / 128), 256, GEMM_SMEM>>>(1, bq, bk, bv);

    cudaFuncSetAttribute(attn_kernel,
                         cudaFuncAttributeMaxDynamicSharedMemorySize, ATTN_SMEM);
    attn_kernel<<<dim3(16, 16, 16), 256, ATTN_SMEM>>>(e_out);

    gemm_kernel<<<dim3(8, MROWS / 128), 256, GEMM_SMEM>>>(0, bo, nullptr, nullptr);

    norm_kernel<<<MROWS, 256>>>(nullptr, n2a, n2b, out, 1, 0);
}

// round 7
// speedup vs baseline: 6.7319x; 1.1244x over previous
#include <cuda_runtime.h>
#include <cuda_fp16.h>
#include <cstdint>

// Problem constants
#define B_   16
#define NE_  512
#define NIN_ 1024
#define H_   16
#define HD_  64
#define MROWS 8192           // B_*NE_
#define KDIM 1024
#define NDIM 1024

// ---------------- scratch (device globals; no allocations allowed) ----------
__device__ __half g_xn[(size_t)MROWS * NIN_];
__device__ __half g_q [(size_t)MROWS * NIN_];   // [B,H,NE,HD]
__device__ __half g_k [(size_t)MROWS * NIN_];
__device__ __half g_v [(size_t)MROWS * NIN_];
__device__ __half g_ao[(size_t)MROWS * NIN_];   // attention output [M,1024]
__device__ float  g_o [(size_t)MROWS * NIN_];   // WO output, pre-norm2 (f32)
__device__ __half g_wr[(size_t)4 * KDIM * NDIM];// fp16 weights (WQ,WK,WV,WO)
__device__ unsigned char g_mask8[(size_t)B_ * NE_ * NE_];
__device__ int   g_mask_kind;                   // 0=u8/bool, 1=int32, 2=float32

// ---------------- helpers ----------------------------------------------------
__device__ __forceinline__ void cp16(void* dst, const void* src)
{
    uint32_t d = (uint32_t)__cvta_generic_to_shared(dst);
    asm volatile("cp.async.cg.shared.global [%0], [%1], 16;\n" :: "r"(d), "l"(src));
}
__device__ __forceinline__ uint32_t smem_u32(const void* p)
{
    uint32_t a;
    asm("{ .reg .u64 t; cvta.to.shared.u64 t, %1; cvt.u32.u64 %0, t; }"
        : "=r"(a) : "l"(p));
    return a;
}
__device__ __forceinline__ void ldm_x4(uint32_t* r, uint32_t addr)
{
    asm volatile("ldmatrix.sync.aligned.m8n8.x4.shared.b16 {%0,%1,%2,%3}, [%4];"
                 : "=r"(r[0]), "=r"(r[1]), "=r"(r[2]), "=r"(r[3]) : "r"(addr));
}
__device__ __forceinline__ void ldm_x4t(uint32_t* r, uint32_t addr)
{
    asm volatile("ldmatrix.sync.aligned.m8n8.x4.trans.shared.b16 {%0,%1,%2,%3}, [%4];"
                 : "=r"(r[0]), "=r"(r[1]), "=r"(r[2]), "=r"(r[3]) : "r"(addr));
}
__device__ __forceinline__ void mma_f16(float* c, const uint32_t* a,
                                        uint32_t b0, uint32_t b1)
{
    asm volatile(
        "mma.sync.aligned.m16n8k16.row.col.f32.f16.f16.f32 "
        "{%0,%1,%2,%3}, {%4,%5,%6,%7}, {%8,%9}, {%0,%1,%2,%3};"
        : "+f"(c[0]), "+f"(c[1]), "+f"(c[2]), "+f"(c[3])
        : "r"(a[0]), "r"(a[1]), "r"(a[2]), "r"(a[3]), "r"(b0), "r"(b1));
}

// ---------------- mask dtype detector ---------------------------------------
__global__ void mask_detect_kernel(const unsigned char* __restrict__ m)
{
    __shared__ int c1s, c2s;
    if (threadIdx.x == 0) { c1s = 0; c2s = 0; }
    __syncthreads();
    int c1 = 0, c2 = 0;
    for (int i = threadIdx.x; i < 16384; i += 256) {
        unsigned char v = m[i];
        int r = i & 3;
        if (v && r != 0) c1++;
        if (v && r <= 1) c2++;
    }
    atomicAdd(&c1s, c1);
    atomicAdd(&c2s, c2);
    __syncthreads();
    if (threadIdx.x == 0)
        g_mask_kind = (c1s == 0) ? 1 : ((c2s == 0) ? 2 : 0);
}

// ---------------- fused prep: mask convert + weight round + norm1 ------------
// blocks [0,4096): mask -> u8 ; [4096,6144): weights f32 -> fp16 ;
// [6144,14336): layernorm1 -> g_xn (half)
__global__ void prep_kernel(const unsigned char* __restrict__ mask,
                            const float* __restrict__ w0, const float* __restrict__ w1,
                            const float* __restrict__ w2, const float* __restrict__ w3,
                            const float* __restrict__ events,
                            const float* __restrict__ alpha,
                            const float* __restrict__ bias)
{
    __shared__ float red[32];
    int blk = blockIdx.x;
    int t = threadIdx.x;

    if (blk < 4096) {
        int kind = g_mask_kind;
        size_t i = ((size_t)blk * 256 + t) * 4;
        uchar4 o;
        if (kind == 1) {
            int4 v = *(const int4*)((const int*)mask + i);
            o.x = v.x != 0; o.y = v.y != 0; o.z = v.z != 0; o.w = v.w != 0;
        } else if (kind == 2) {
            float4 v = *(const float4*)((const float*)mask + i);
            o.x = v.x != 0.f; o.y = v.y != 0.f; o.z = v.z != 0.f; o.w = v.w != 0.f;
        } else {
            uchar4 v = *(const uchar4*)(mask + i);
            o.x = v.x != 0; o.y = v.y != 0; o.z = v.z != 0; o.w = v.w != 0;
        }
        *(uchar4*)(g_mask8 + i) = o;
        return;
    }
    blk -= 4096;
    if (blk < 2048) {
        int sel = blk >> 9;
        const float* src = sel == 0 ? w0 : sel == 1 ? w1 : sel == 2 ? w2 : w3;
        size_t i = (((size_t)(blk & 511) * 256) + t) * 8;
        __half* dst = g_wr + (size_t)sel * KDIM * NDIM;
        float4 v0 = *(const float4*)(src + i);
        float4 v1 = *(const float4*)(src + i + 4);
        __half2 h[4];
        h[0] = __floats2half2_rn(v0.x, v0.y);
        h[1] = __floats2half2_rn(v0.z, v0.w);
        h[2] = __floats2half2_rn(v1.x, v1.y);
        h[3] = __floats2half2_rn(v1.z, v1.w);
        *(uint4*)(dst + i) = *(const uint4*)h;
        return;
    }
    // ---- layernorm1 ----
    int row = blk - 2048;
    const float* xr = events + (size_t)row * 1024;
    float v[4];
    float s = 0.f, ss = 0.f;
#pragma unroll
    for (int i = 0; i < 4; i++) {
        v[i] = xr[t + i * 256];
        s += v[i];
        ss += v[i] * v[i];
    }
#pragma unroll
    for (int o = 16; o; o >>= 1) {
        s  += __shfl_xor_sync(0xffffffffu, s,  o);
        ss += __shfl_xor_sync(0xffffffffu, ss, o);
    }
    int w = t >> 5, l = t & 31;
    if (l == 0) { red[w] = s; red[w + 8] = ss; }
    __syncthreads();
    if (w == 0) {
        float s2  = (l < 8) ? red[l]     : 0.f;
        float ss2 = (l < 8) ? red[l + 8] : 0.f;
#pragma unroll
        for (int o = 4; o; o >>= 1) {
            s2  += __shfl_xor_sync(0xffffffffu, s2,  o);
            ss2 += __shfl_xor_sync(0xffffffffu, ss2, o);
        }
        if (l == 0) { red[16] = s2; red[17] = ss2; }
    }
    __syncthreads();
    float mean = red[16] * (1.f / 1024.f);
    float var  = (red[17] - 1024.f * mean * mean) * (1.f / 1023.f);
    var = fmaxf(var, 0.f);
    float inv = 1.f / (sqrtf(var) + 1e-6f);
    __half* yr = g_xn + (size_t)row * 1024;
#pragma unroll
    for (int i = 0; i < 4; i++) {
        int c = t + i * 256;
        yr[c] = __float2half_rn(alpha[c] * (v[i] - mean) * inv + bias[c]);
    }
}

// ---------------- layernorm2 (f32 in g_o -> f32 out) -------------------------
__global__ void norm2_kernel(const float* __restrict__ alpha,
                             const float* __restrict__ bias,
                             float* __restrict__ yout)
{
    int row = blockIdx.x;
    const float* xr = g_o + (size_t)row * 1024;
    float* yr = yout + (size_t)row * 1024;
    int t = threadIdx.x;
    float v[4];
    float s = 0.f, ss = 0.f;
#pragma unroll
    for (int i = 0; i < 4; i++) {
        v[i] = xr[t + i * 256];
        s += v[i];
        ss += v[i] * v[i];
    }
#pragma unroll
    for (int o = 16; o; o >>= 1) {
        s  += __shfl_xor_sync(0xffffffffu, s,  o);
        ss += __shfl_xor_sync(0xffffffffu, ss, o);
    }
    __shared__ float red[32];
    int w = t >> 5, l = t & 31;
    if (l == 0) { red[w] = s; red[w + 8] = ss; }
    __syncthreads();
    if (w == 0) {
        float s2  = (l < 8) ? red[l]     : 0.f;
        float ss2 = (l < 8) ? red[l + 8] : 0.f;
#pragma unroll
        for (int o = 4; o; o >>= 1) {
            s2  += __shfl_xor_sync(0xffffffffu, s2,  o);
            ss2 += __shfl_xor_sync(0xffffffffu, ss2, o);
        }
        if (l == 0) { red[16] = s2; red[17] = ss2; }
    }
    __syncthreads();
    float mean = red[16] * (1.f / 1024.f);
    float var  = (red[17] - 1024.f * mean * mean) * (1.f / 1023.f);
    var = fmaxf(var, 0.f);
    float inv = 1.f / (sqrtf(var) + 1e-6f);
#pragma unroll
    for (int i = 0; i < 4; i++) {
        int c = t + i * 256;
        yr[c] = alpha[c] * (v[i] - mean) * inv + bias[c];
    }
}

// ---------------- fp16 tensor-core GEMM --------------------------------------
// C[M,N] = A[M,K] @ W[N,K]^T + bias. BM=128, BN=128, BK=64, 3-stage cp.async,
// 8 warps x (64x32) tiles via m16n8k16 fp16 MMA + ldmatrix.
#define GA_STRIDE 144                 // bytes per 64-half row (72 halfs)
#define GA_TILE   (128 * GA_STRIDE)   // 18432 B
#define G_STAGE   (2 * GA_TILE)       // A+B per stage
#define GEMM_SMEM (3 * G_STAGE)       // 110592 B

__global__ void __launch_bounds__(256, 2)
gemm_kernel(int qkv_mode,
            const float* __restrict__ bias0,
            const float* __restrict__ bias1,
            const float* __restrict__ bias2)
{
    extern __shared__ char sh[];
    const uint32_t shb = smem_u32(sh);

    int w_sel, colBase;
    const __half* A;
    const float* bias;
    __half* Ch = nullptr;
    float* Cf = nullptr;
    int remap;
    if (qkv_mode) {
        w_sel   = blockIdx.x >> 3;
        colBase = (blockIdx.x & 7) * 128;
        A    = g_xn;
        bias = (w_sel == 0) ? bias0 : (w_sel == 1) ? bias1 : bias2;
        Ch   = (w_sel == 0) ? g_q : (w_sel == 1) ? g_k : g_v;
        remap = 1;
    } else {
        w_sel   = 3;
        colBase = blockIdx.x * 128;
        A    = g_ao;
        bias = bias0;
        Cf   = g_o;
        remap = 0;
    }
    const __half* W = g_wr + (size_t)w_sel * KDIM * NDIM;

    const int tid = threadIdx.x;
    const int wid = tid >> 5, lane = tid & 31;
    const int wm = wid & 1, wn = wid >> 1;
    const int m0 = wm * 64, n0 = wn * 32;
    const int lr = lane >> 2, lc = lane & 3;
    const int rowBase = blockIdx.y * 128;

    const __half* Ab = A + (size_t)rowBase * KDIM;
    const __half* Wb = W + (size_t)colBase * KDIM;

    float acc[4][4][4];
#pragma unroll
    for (int i = 0; i < 4; i++)
#pragma unroll
        for (int j = 0; j < 4; j++)
#pragma unroll
            for (int q = 0; q < 4; q++) acc[i][j][q] = 0.f;

    auto loadChunk = [&](int kt) {
        char* sA = sh + (kt % 3) * G_STAGE;
        char* sB = sA + GA_TILE;
#pragma unroll
        for (int i = 0; i < 4; i++) {
            int g = tid + i * 256;
            int r = g >> 3, c = g & 7;
            cp16(sA + r * GA_STRIDE + c * 16, Ab + (size_t)r * KDIM + kt * 64 + c * 8);
        }
#pragma unroll
        for (int i = 0; i < 4; i++) {
            int g = tid + i * 256;
            int r = g >> 3, c = g & 7;
            cp16(sB + r * GA_STRIDE + c * 16, Wb + (size_t)r * KDIM + kt * 64 + c * 8);
        }
        asm volatile("cp.async.commit_group;\n");
    };

    const int NK = KDIM / 64;   // 16
    loadChunk(0);
    loadChunk(1);

    const int aRow = lane & 15, aColH = (lane >> 4) << 3;
    const int bRow = ((lane >> 4) << 3) + (lane & 7);
    const int bColH = ((lane >> 3) & 1) << 3;

    for (int kt = 0; kt < NK; kt++) {
        if (kt + 1 < NK) { asm volatile("cp.async.wait_group 1;\n"); }
        else             { asm volatile("cp.async.wait_group 0;\n"); }
        __syncthreads();
        if (kt + 2 < NK) loadChunk(kt + 2);

        const uint32_t sAb = shb + (kt % 3) * G_STAGE;
        const uint32_t sBb = sAb + GA_TILE;

#pragma unroll
        for (int k16 = 0; k16 < 4; k16++) {
            uint32_t a[4][4], b[2][4];
#pragma unroll
            for (int mi = 0; mi < 4; mi++)
                ldm_x4(a[mi], sAb + (m0 + 16 * mi + aRow) * GA_STRIDE +
                              (k16 * 16 + aColH) * 2);
#pragma unroll
            for (int ni2 = 0; ni2 < 2; ni2++)
                ldm_x4(b[ni2], sBb + (n0 + ni2 * 16 + bRow) * GA_STRIDE +
                               (k16 * 16 + bColH) * 2);
#pragma unroll
            for (int mi = 0; mi < 4; mi++)
#pragma unroll
                for (int ni = 0; ni < 4; ni++)
                    mma_f16(acc[mi][ni], a[mi],
                            b[ni >> 1][(ni & 1) * 2], b[ni >> 1][(ni & 1) * 2 + 1]);
        }
        __syncthreads();
    }

#pragma unroll
    for (int mi = 0; mi < 4; mi++) {
#pragma unroll
        for (int ni = 0; ni < 4; ni++) {
            int row0 = rowBase + m0 + 16 * mi + lr;
            int col0 = colBase + n0 + 8 * ni + 2 * lc;
            float b0 = bias[col0], b1 = bias[col0 + 1];
            float v00 = acc[mi][ni][0] + b0;
            float v01 = acc[mi][ni][1] + b1;
            float v10 = acc[mi][ni][2] + b0;
            float v11 = acc[mi][ni][3] + b1;
            if (remap) {
                int bidx = row0 >> 9, e = row0 & 511;
                int hh = col0 >> 6,  d = col0 & 63;
                size_t base0 = (((size_t)(bidx * 16 + hh) * 512) + e) * 64 + d;
                *(__half2*)&Ch[base0]               = __floats2half2_rn(v00, v01);
                *(__half2*)&Ch[base0 + (size_t)512] = __floats2half2_rn(v10, v11);
            } else {
                *(float2*)&Cf[(size_t)row0 * NDIM + col0]       = make_float2(v00, v01);
                *(float2*)&Cf[(size_t)(row0 + 8) * NDIM + col0] = make_float2(v10, v11);
            }
        }
    }
}

// ---------------- attention (fp16 tensor-core, double-buffered K/V) ----------
// Per (b,h,32-q-tile): S = (Q/8)@K^T, exact masked softmax (f32), write e (f32),
// O^T = V^T @ E^T with on-the-fly f32->half B fragments. 256 threads, 2 CTAs/SM.
#define A_STRIDE 144                  // bytes per 64-half row
#define OFF_Q    0                    // 32 x 144 = 4608
#define OFF_KV0  4608                 // buf0: 128 x 144 = 18432
#define KVBUF    18432
#define OFF_S    41472                // 32 x 520 f32 = 66560
#define SST      520
#define OFF_INV  108032               // 32 f32
#define ATTN_SMEM 108160

__global__ void __launch_bounds__(256, 2)
attn_kernel(float* __restrict__ e_out)
{
    extern __shared__ char sh[];
    const uint32_t shb = smem_u32(sh);
    __half* sQ   = (__half*)(sh + OFF_Q);
    float*  sS   = (float*)(sh + OFF_S);
    float*  sInv = (float*)(sh + OFF_INV);

    const int qt = blockIdx.x, h = blockIdx.y, b = blockIdx.z;
    const int tid = threadIdx.x;
    const int lane = tid & 31, wid = tid >> 5;
    const int lr = lane >> 2, lc = lane & 3;
    const int q0 = qt * 32;

    const __half* Q  = g_q + (size_t)(b * 16 + h) * 512 * 64;
    const __half* Kp = g_k + (size_t)(b * 16 + h) * 512 * 64;
    const __half* Vp = g_v + (size_t)(b * 16 + h) * 512 * 64;

    // ---- load Q tile scaled by 1/8 (exact in fp16) ----
    {
        const __half2 sc = __half2half2(__float2half(0.125f));
        int r = tid >> 3, c8 = tid & 7;
        uint4 raw = *(const uint4*)(Q + (size_t)(q0 + r) * 64 + c8 * 8);
        __half2* hp = (__half2*)&raw;
#pragma unroll
        for (int j = 0; j < 4; j++) hp[j] = __hmul2(hp[j], sc);
        *(uint4*)((char*)sQ + r * A_STRIDE + c8 * 16) = raw;
    }

    const int aRow = lane & 15, aColH = (lane >> 4) << 3;
    const int bRow = ((lane >> 4) << 3) + (lane & 7);
    const int bColH = ((lane >> 3) & 1) << 3;

    auto loadKV = [&](const __half* src, int c) {
        char* dst = sh + OFF_KV0 + (c & 1) * KVBUF;
#pragma unroll
        for (int i = 0; i < 4; i++) {
            int g = tid + i * 256;
            int r = g >> 3, cc = g & 7;
            cp16(dst + r * A_STRIDE + cc * 16,
                 src + (size_t)(c * 128 + r) * 64 + cc * 8);
        }
        asm volatile("cp.async.commit_group;\n");
    };

    // ---- scores: S[32,512], K double-buffered ----
    const int wm = wid & 1, wn = wid >> 1;
    loadKV(Kp, 0);
    for (int c = 0; c < 4; c++) {
        __syncthreads();                 // protect buffer being overwritten
        if (c < 3) loadKV(Kp, c + 1);
        if (c < 3) { asm volatile("cp.async.wait_group 1;\n"); }
        else       { asm volatile("cp.async.wait_group 0;\n"); }
        __syncthreads();

        const uint32_t kvb = shb + OFF_KV0 + (c & 1) * KVBUF;
        float acc[4][4] = {};
#pragma unroll
        for (int k16 = 0; k16 < 4; k16++) {
            uint32_t a[4], bf[2][4];
            ldm_x4(a, shb + OFF_Q + (wm * 16 + aRow) * A_STRIDE +
                      (k16 * 16 + aColH) * 2);
#pragma unroll
            for (int ni2 = 0; ni2 < 2; ni2++)
                ldm_x4(bf[ni2], kvb + (wn * 32 + ni2 * 16 + bRow) * A_STRIDE +
                               (k16 * 16 + bColH) * 2);
#pragma unroll
            for (int ni = 0; ni < 4; ni++)
                mma_f16(acc[ni], a, bf[ni >> 1][(ni & 1) * 2],
                        bf[ni >> 1][(ni & 1) * 2 + 1]);
        }
        const int row = wm * 16 + lr;
        const int kb = c * 128;
#pragma unroll
        for (int ni = 0; ni < 4; ni++) {
            int col = kb + wn * 32 + ni * 8 + 2 * lc;
            sS[row * SST + col]           = acc[ni][0];
            sS[row * SST + col + 1]       = acc[ni][1];
            sS[(row + 8) * SST + col]     = acc[ni][2];
            sS[(row + 8) * SST + col + 1] = acc[ni][3];
        }
    }

    // ---- prefetch V chunk 0 into buf0 (K buf0 dead: last K mma used buf1) ----
    loadKV(Vp, 0);
    __syncthreads();   // sS complete for softmax

    // ---- masked softmax (8 warps x 4 rows), exact f32 ----
    const float NEGINF = __int_as_float(0xff800000);
    const unsigned char* mbase = g_mask8 + ((size_t)b * 512 + q0) * 512;
#pragma unroll
    for (int rr = 0; rr < 4; rr++) {
        int r = wid * 4 + rr;
        float* srow = sS + r * SST;
        const unsigned char* mr = mbase + (size_t)r * 512;
        unsigned int mbits = 0;
        float mx = NEGINF;
#pragma unroll
        for (int i = 0; i < 16; i++) {
            int k = lane + 32 * i;
            if (mr[k]) mbits |= (1u << i);
            else       mx = fmaxf(mx, srow[k]);
        }
#pragma unroll
        for (int o = 16; o; o >>= 1) mx = fmaxf(mx, __shfl_xor_sync(0xffffffffu, mx, o));
        float sum = 0.f;
#pragma unroll
        for (int i = 0; i < 16; i++) {
            int k = lane + 32 * i;
            float ev = (mbits >> i) & 1 ? 0.f : __expf(srow[k] - mx);
            srow[k] = ev;
            sum += ev;
        }
#pragma unroll
        for (int o = 16; o; o >>= 1) sum += __shfl_xor_sync(0xffffffffu, sum, o);
        if (lane == 0) sInv[r] = 1.f / sum;
    }
    __syncthreads();

    // ---- write e (normalized f32), coalesced, streaming ----
    float* erow = e_out + (((size_t)(b * 16 + h) * 512) + q0) * 512;
#pragma unroll
    for (int i = 0; i < 16; i++) {
        int idx = tid + i * 256;
        int r = idx >> 7;
        int c = (idx & 127) * 4;
        float inv = sInv[r];
        float4 v = *(const float4*)&sS[r * SST + c];
        v.x *= inv; v.y *= inv; v.z *= inv; v.w *= inv;
        __stcs((float4*)(erow + (size_t)r * 512 + c), v);
    }

    // ---- O^T = V^T @ E^T, V double-buffered, E f32->half on the fly ----
    const int wd = wid & 3, wq = wid >> 2;
    const int d0 = wd * 16, qb = wq * 16;
    float oacc[2][4] = {};
    for (int c = 0; c < 4; c++) {
        __syncthreads();
        if (c < 3) loadKV(Vp, c + 1);
        if (c < 3) { asm volatile("cp.async.wait_group 1;\n"); }
        else       { asm volatile("cp.async.wait_group 0;\n"); }
        __syncthreads();

        const uint32_t kvb = shb + OFF_KV0 + (c & 1) * KVBUF;
        const int kb = c * 128;
#pragma unroll
        for (int k16 = 0; k16 < 8; k16++) {
            uint32_t a[4];
            ldm_x4t(a, kvb + (k16 * 16 + bRow) * A_STRIDE + (d0 + bColH) * 2);
#pragma unroll
            for (int ni = 0; ni < 2; ni++) {
                int n = qb + ni * 8 + lr;
                const float* pe = sS + n * SST + kb + k16 * 16 + lc * 2;
                float2 e0 = *(const float2*)pe;
                float2 e1 = *(const float2*)(pe + 8);
                __half2 h0 = __floats2half2_rn(e0.x, e0.y);
                __half2 h1 = __floats2half2_rn(e1.x, e1.y);
                mma_f16(oacc[ni], a, *(const uint32_t*)&h0, *(const uint32_t*)&h1);
            }
        }
    }
    __syncthreads();

    // ---- normalize, stage O[q][d] as half in sQ region, write coalesced ----
    __half* sO = sQ;
#pragma unroll
    for (int ni = 0; ni < 2; ni++) {
        int q = qb + ni * 8 + 2 * lc;
        float i0 = sInv[q], i1 = sInv[q + 1];
        sO[q * 72 + d0 + lr]           = __float2half_rn(oacc[ni][0] * i0);
        sO[(q + 1) * 72 + d0 + lr]     = __float2half_rn(oacc[ni][1] * i1);
        sO[q * 72 + d0 + lr + 8]       = __float2half_rn(oacc[ni][2] * i0);
        sO[(q + 1) * 72 + d0 + lr + 8] = __float2half_rn(oacc[ni][3] * i1);
    }
    __syncthreads();
    {
        int r = tid >> 3, c = tid & 7;
        uint4 v = *(const uint4*)((const char*)sO + r * A_STRIDE + c * 16);
        *(uint4*)(g_ao + ((size_t)(b * 512 + q0 + r)) * 1024 + h * 64 + c * 8) = v;
    }
}

// ---------------- launch ------------------------------------------------------
extern "C" void kernel_launch(void* const* d_in, const int* in_sizes, int n_in,
                              void* d_out, int out_size)
{
    const float*         events = (const float*)d_in[0];
    const unsigned char* mask   = (const unsigned char*)d_in[1];
    const float*         n1a    = (const float*)d_in[2];
    const float*         n1b    = (const float*)d_in[3];
    const float*         wq     = (const float*)d_in[4];
    const float*         bq     = (const float*)d_in[5];
    const float*         wk     = (const float*)d_in[6];
    const float*         bk     = (const float*)d_in[7];
    const float*         wv     = (const float*)d_in[8];
    const float*         bv     = (const float*)d_in[9];
    const float*         wo     = (const float*)d_in[10];
    const float*         bo     = (const float*)d_in[11];
    const float*         n2a    = (const float*)d_in[12];
    const float*         n2b    = (const float*)d_in[13];

    float* out   = (float*)d_out;                       // [16,512,1024]
    float* e_out = out + (size_t)MROWS * 1024;          // [16,16,512,512]

    mask_detect_kernel<<<1, 256>>>(mask);
    prep_kernel<<<4096 + 2048 + MROWS, 256>>>(mask, wq, wk, wv, wo,
                                              events, n1a, n1b);

    cudaFuncSetAttribute(gemm_kernel,
                         cudaFuncAttributeMaxDynamicSharedMemorySize, GEMM_SMEM);
    gemm_kernel<<<dim3(24, MROWS / 128), 256, GEMM_SMEM>>>(1, bq, bk, bv);

    cudaFuncSetAttribute(attn_kernel,
                         cudaFuncAttributeMaxDynamicSharedMemorySize, ATTN_SMEM);
    attn_kernel<<<dim3(16, 16, 16), 256, ATTN_SMEM>>>(e_out);

    gemm_kernel<<<dim3(8, MROWS / 128), 256, GEMM_SMEM>>>(0, bo, nullptr, nullptr);

    norm2_kernel<<<MROWS, 256>>>(n2a, n2b, out);
}

// round 8
// speedup vs baseline: 7.3780x; 1.0960x over previous
#include <cuda_runtime.h>
#include <cuda_fp16.h>
#include <cstdint>

// Problem constants
#define B_   16
#define NE_  512
#define NIN_ 1024
#define H_   16
#define HD_  64
#define MROWS 8192           // B_*NE_
#define KDIM 1024
#define NDIM 1024

// ---------------- scratch (device globals; no allocations allowed) ----------
__device__ __half g_xn[(size_t)MROWS * NIN_];
__device__ __half g_q [(size_t)MROWS * NIN_];   // [B,H,NE,HD]
__device__ __half g_k [(size_t)MROWS * NIN_];
__device__ __half g_v [(size_t)MROWS * NIN_];
__device__ __half g_ao[(size_t)MROWS * NIN_];   // attention output [M,1024]
__device__ float  g_o [(size_t)MROWS * NIN_];   // WO output, pre-norm2 (f32)
__device__ __half g_wr[(size_t)4 * KDIM * NDIM];// fp16 weights (WQ,WK,WV,WO)
__device__ unsigned char g_mask8[(size_t)B_ * NE_ * NE_];
__device__ int   g_mask_kind;                   // 0=u8/bool, 1=int32, 2=float32

// ---------------- helpers ----------------------------------------------------
__device__ __forceinline__ void cp16(void* dst, const void* src)
{
    uint32_t d = (uint32_t)__cvta_generic_to_shared(dst);
    asm volatile("cp.async.cg.shared.global [%0], [%1], 16;\n" :: "r"(d), "l"(src));
}
__device__ __forceinline__ uint32_t smem_u32(const void* p)
{
    uint32_t a;
    asm("{ .reg .u64 t; cvta.to.shared.u64 t, %1; cvt.u32.u64 %0, t; }"
        : "=r"(a) : "l"(p));
    return a;
}
__device__ __forceinline__ void ldm_x4(uint32_t* r, uint32_t addr)
{
    asm volatile("ldmatrix.sync.aligned.m8n8.x4.shared.b16 {%0,%1,%2,%3}, [%4];"
                 : "=r"(r[0]), "=r"(r[1]), "=r"(r[2]), "=r"(r[3]) : "r"(addr));
}
__device__ __forceinline__ void ldm_x4t(uint32_t* r, uint32_t addr)
{
    asm volatile("ldmatrix.sync.aligned.m8n8.x4.trans.shared.b16 {%0,%1,%2,%3}, [%4];"
                 : "=r"(r[0]), "=r"(r[1]), "=r"(r[2]), "=r"(r[3]) : "r"(addr));
}
__device__ __forceinline__ void mma_f16(float* c, const uint32_t* a,
                                        uint32_t b0, uint32_t b1)
{
    asm volatile(
        "mma.sync.aligned.m16n8k16.row.col.f32.f16.f16.f32 "
        "{%0,%1,%2,%3}, {%4,%5,%6,%7}, {%8,%9}, {%0,%1,%2,%3};"
        : "+f"(c[0]), "+f"(c[1]), "+f"(c[2]), "+f"(c[3])
        : "r"(a[0]), "r"(a[1]), "r"(a[2]), "r"(a[3]), "r"(b0), "r"(b1));
}

// ---------------- mask dtype detector ---------------------------------------
__global__ void mask_detect_kernel(const unsigned char* __restrict__ m)
{
    __shared__ int c1s, c2s;
    if (threadIdx.x == 0) { c1s = 0; c2s = 0; }
    __syncthreads();
    int c1 = 0, c2 = 0;
    for (int i = threadIdx.x; i < 16384; i += 256) {
        unsigned char v = m[i];
        int r = i & 3;
        if (v && r != 0) c1++;
        if (v && r <= 1) c2++;
    }
    atomicAdd(&c1s, c1);
    atomicAdd(&c2s, c2);
    __syncthreads();
    if (threadIdx.x == 0)
        g_mask_kind = (c1s == 0) ? 1 : ((c2s == 0) ? 2 : 0);
}

// ---------------- fused prep: mask convert + weight round + norm1 ------------
__global__ void prep_kernel(const unsigned char* __restrict__ mask,
                            const float* __restrict__ w0, const float* __restrict__ w1,
                            const float* __restrict__ w2, const float* __restrict__ w3,
                            const float* __restrict__ events,
                            const float* __restrict__ alpha,
                            const float* __restrict__ bias)
{
    __shared__ float red[32];
    int blk = blockIdx.x;
    int t = threadIdx.x;

    if (blk < 4096) {
        int kind = g_mask_kind;
        size_t i = ((size_t)blk * 256 + t) * 4;
        uchar4 o;
        if (kind == 1) {
            int4 v = *(const int4*)((const int*)mask + i);
            o.x = v.x != 0; o.y = v.y != 0; o.z = v.z != 0; o.w = v.w != 0;
        } else if (kind == 2) {
            float4 v = *(const float4*)((const float*)mask + i);
            o.x = v.x != 0.f; o.y = v.y != 0.f; o.z = v.z != 0.f; o.w = v.w != 0.f;
        } else {
            uchar4 v = *(const uchar4*)(mask + i);
            o.x = v.x != 0; o.y = v.y != 0; o.z = v.z != 0; o.w = v.w != 0;
        }
        *(uchar4*)(g_mask8 + i) = o;
        return;
    }
    blk -= 4096;
    if (blk < 2048) {
        int sel = blk >> 9;
        const float* src = sel == 0 ? w0 : sel == 1 ? w1 : sel == 2 ? w2 : w3;
        size_t i = (((size_t)(blk & 511) * 256) + t) * 8;
        __half* dst = g_wr + (size_t)sel * KDIM * NDIM;
        float4 v0 = *(const float4*)(src + i);
        float4 v1 = *(const float4*)(src + i + 4);
        __half2 h[4];
        h[0] = __floats2half2_rn(v0.x, v0.y);
        h[1] = __floats2half2_rn(v0.z, v0.w);
        h[2] = __floats2half2_rn(v1.x, v1.y);
        h[3] = __floats2half2_rn(v1.z, v1.w);
        *(uint4*)(dst + i) = *(const uint4*)h;
        return;
    }
    // ---- layernorm1 ----
    int row = blk - 2048;
    const float* xr = events + (size_t)row * 1024;
    float v[4];
    float s = 0.f, ss = 0.f;
#pragma unroll
    for (int i = 0; i < 4; i++) {
        v[i] = xr[t + i * 256];
        s += v[i];
        ss += v[i] * v[i];
    }
#pragma unroll
    for (int o = 16; o; o >>= 1) {
        s  += __shfl_xor_sync(0xffffffffu, s,  o);
        ss += __shfl_xor_sync(0xffffffffu, ss, o);
    }
    int w = t >> 5, l = t & 31;
    if (l == 0) { red[w] = s; red[w + 8] = ss; }
    __syncthreads();
    if (w == 0) {
        float s2  = (l < 8) ? red[l]     : 0.f;
        float ss2 = (l < 8) ? red[l + 8] : 0.f;
#pragma unroll
        for (int o = 4; o; o >>= 1) {
            s2  += __shfl_xor_sync(0xffffffffu, s2,  o);
            ss2 += __shfl_xor_sync(0xffffffffu, ss2, o);
        }
        if (l == 0) { red[16] = s2; red[17] = ss2; }
    }
    __syncthreads();
    float mean = red[16] * (1.f / 1024.f);
    float var  = (red[17] - 1024.f * mean * mean) * (1.f / 1023.f);
    var = fmaxf(var, 0.f);
    float inv = 1.f / (sqrtf(var) + 1e-6f);
    __half* yr = g_xn + (size_t)row * 1024;
#pragma unroll
    for (int i = 0; i < 4; i++) {
        int c = t + i * 256;
        yr[c] = __float2half_rn(alpha[c] * (v[i] - mean) * inv + bias[c]);
    }
}

// ---------------- layernorm2 (f32 in g_o -> f32 out) -------------------------
__global__ void norm2_kernel(const float* __restrict__ alpha,
                             const float* __restrict__ bias,
                             float* __restrict__ yout)
{
    int row = blockIdx.x;
    const float* xr = g_o + (size_t)row * 1024;
    float* yr = yout + (size_t)row * 1024;
    int t = threadIdx.x;
    float v[4];
    float s = 0.f, ss = 0.f;
#pragma unroll
    for (int i = 0; i < 4; i++) {
        v[i] = xr[t + i * 256];
        s += v[i];
        ss += v[i] * v[i];
    }
#pragma unroll
    for (int o = 16; o; o >>= 1) {
        s  += __shfl_xor_sync(0xffffffffu, s,  o);
        ss += __shfl_xor_sync(0xffffffffu, ss, o);
    }
    __shared__ float red[32];
    int w = t >> 5, l = t & 31;
    if (l == 0) { red[w] = s; red[w + 8] = ss; }
    __syncthreads();
    if (w == 0) {
        float s2  = (l < 8) ? red[l]     : 0.f;
        float ss2 = (l < 8) ? red[l + 8] : 0.f;
#pragma unroll
        for (int o = 4; o; o >>= 1) {
            s2  += __shfl_xor_sync(0xffffffffu, s2,  o);
            ss2 += __shfl_xor_sync(0xffffffffu, ss2, o);
        }
        if (l == 0) { red[16] = s2; red[17] = ss2; }
    }
    __syncthreads();
    float mean = red[16] * (1.f / 1024.f);
    float var  = (red[17] - 1024.f * mean * mean) * (1.f / 1023.f);
    var = fmaxf(var, 0.f);
    float inv = 1.f / (sqrtf(var) + 1e-6f);
#pragma unroll
    for (int i = 0; i < 4; i++) {
        int c = t + i * 256;
        yr[c] = alpha[c] * (v[i] - mean) * inv + bias[c];
    }
}

// ---------------- fp16 tensor-core GEMM --------------------------------------
#define GA_STRIDE 144                 // bytes per 64-half row (72 halfs)
#define GA_TILE   (128 * GA_STRIDE)   // 18432 B
#define G_STAGE   (2 * GA_TILE)       // A+B per stage
#define GEMM_SMEM (3 * G_STAGE)       // 110592 B

__global__ void __launch_bounds__(256, 2)
gemm_kernel(int qkv_mode,
            const float* __restrict__ bias0,
            const float* __restrict__ bias1,
            const float* __restrict__ bias2)
{
    extern __shared__ char sh[];
    const uint32_t shb = smem_u32(sh);

    int w_sel, colBase;
    const __half* A;
    const float* bias;
    __half* Ch = nullptr;
    float* Cf = nullptr;
    int remap;
    if (qkv_mode) {
        w_sel   = blockIdx.x >> 3;
        colBase = (blockIdx.x & 7) * 128;
        A    = g_xn;
        bias = (w_sel == 0) ? bias0 : (w_sel == 1) ? bias1 : bias2;
        Ch   = (w_sel == 0) ? g_q : (w_sel == 1) ? g_k : g_v;
        remap = 1;
    } else {
        w_sel   = 3;
        colBase = blockIdx.x * 128;
        A    = g_ao;
        bias = bias0;
        Cf   = g_o;
        remap = 0;
    }
    const __half* W = g_wr + (size_t)w_sel * KDIM * NDIM;

    const int tid = threadIdx.x;
    const int wid = tid >> 5, lane = tid & 31;
    const int wm = wid & 1, wn = wid >> 1;
    const int m0 = wm * 64, n0 = wn * 32;
    const int lr = lane >> 2, lc = lane & 3;
    const int rowBase = blockIdx.y * 128;

    const __half* Ab = A + (size_t)rowBase * KDIM;
    const __half* Wb = W + (size_t)colBase * KDIM;

    float acc[4][4][4];
#pragma unroll
    for (int i = 0; i < 4; i++)
#pragma unroll
        for (int j = 0; j < 4; j++)
#pragma unroll
            for (int q = 0; q < 4; q++) acc[i][j][q] = 0.f;

    auto loadChunk = [&](int kt) {
        char* sA = sh + (kt % 3) * G_STAGE;
        char* sB = sA + GA_TILE;
#pragma unroll
        for (int i = 0; i < 4; i++) {
            int g = tid + i * 256;
            int r = g >> 3, c = g & 7;
            cp16(sA + r * GA_STRIDE + c * 16, Ab + (size_t)r * KDIM + kt * 64 + c * 8);
        }
#pragma unroll
        for (int i = 0; i < 4; i++) {
            int g = tid + i * 256;
            int r = g >> 3, c = g & 7;
            cp16(sB + r * GA_STRIDE + c * 16, Wb + (size_t)r * KDIM + kt * 64 + c * 8);
        }
        asm volatile("cp.async.commit_group;\n");
    };

    const int NK = KDIM / 64;   // 16
    loadChunk(0);
    loadChunk(1);

    const int aRow = lane & 15, aColH = (lane >> 4) << 3;
    const int bRow = ((lane >> 4) << 3) + (lane & 7);
    const int bColH = ((lane >> 3) & 1) << 3;

    for (int kt = 0; kt < NK; kt++) {
        if (kt + 1 < NK) { asm volatile("cp.async.wait_group 1;\n"); }
        else             { asm volatile("cp.async.wait_group 0;\n"); }
        __syncthreads();
        if (kt + 2 < NK) loadChunk(kt + 2);

        const uint32_t sAb = shb + (kt % 3) * G_STAGE;
        const uint32_t sBb = sAb + GA_TILE;

#pragma unroll
        for (int k16 = 0; k16 < 4; k16++) {
            uint32_t a[4][4], b[2][4];
#pragma unroll
            for (int mi = 0; mi < 4; mi++)
                ldm_x4(a[mi], sAb + (m0 + 16 * mi + aRow) * GA_STRIDE +
                              (k16 * 16 + aColH) * 2);
#pragma unroll
            for (int ni2 = 0; ni2 < 2; ni2++)
                ldm_x4(b[ni2], sBb + (n0 + ni2 * 16 + bRow) * GA_STRIDE +
                               (k16 * 16 + bColH) * 2);
#pragma unroll
            for (int mi = 0; mi < 4; mi++)
#pragma unroll
                for (int ni = 0; ni < 4; ni++)
                    mma_f16(acc[mi][ni], a[mi],
                            b[ni >> 1][(ni & 1) * 2], b[ni >> 1][(ni & 1) * 2 + 1]);
        }
        __syncthreads();
    }

#pragma unroll
    for (int mi = 0; mi < 4; mi++) {
#pragma unroll
        for (int ni = 0; ni < 4; ni++) {
            int row0 = rowBase + m0 + 16 * mi + lr;
            int col0 = colBase + n0 + 8 * ni + 2 * lc;
            float b0 = bias[col0], b1 = bias[col0 + 1];
            float v00 = acc[mi][ni][0] + b0;
            float v01 = acc[mi][ni][1] + b1;
            float v10 = acc[mi][ni][2] + b0;
            float v11 = acc[mi][ni][3] + b1;
            if (remap) {
                int bidx = row0 >> 9, e = row0 & 511;
                int hh = col0 >> 6,  d = col0 & 63;
                size_t base0 = (((size_t)(bidx * 16 + hh) * 512) + e) * 64 + d;
                *(__half2*)&Ch[base0]               = __floats2half2_rn(v00, v01);
                *(__half2*)&Ch[base0 + (size_t)512] = __floats2half2_rn(v10, v11);
            } else {
                *(float2*)&Cf[(size_t)row0 * NDIM + col0]       = make_float2(v00, v01);
                *(float2*)&Cf[(size_t)(row0 + 8) * NDIM + col0] = make_float2(v10, v11);
            }
        }
    }
}

// ---------------- attention (fp16 tensor-core, fused softmax+e-write) --------
#define A_STRIDE 144                  // bytes per 64-half row
#define OFF_Q    0                    // 32 x 144 = 4608
#define OFF_KV0  4608                 // buf0: 128 x 144 = 18432
#define KVBUF    18432
#define OFF_S    41472                // 32 x 520 f32 = 66560
#define SST      520
#define OFF_INV  108032               // 32 f32
#define ATTN_SMEM 108160

__global__ void __launch_bounds__(256, 2)
attn_kernel(float* __restrict__ e_out)
{
    extern __shared__ char sh[];
    const uint32_t shb = smem_u32(sh);
    __half* sQ   = (__half*)(sh + OFF_Q);
    float*  sS   = (float*)(sh + OFF_S);
    float*  sInv = (float*)(sh + OFF_INV);

    const int qt = blockIdx.x, h = blockIdx.y, b = blockIdx.z;
    const int tid = threadIdx.x;
    const int lane = tid & 31, wid = tid >> 5;
    const int lr = lane >> 2, lc = lane & 3;
    const int q0 = qt * 32;

    const __half* Q  = g_q + (size_t)(b * 16 + h) * 512 * 64;
    const __half* Kp = g_k + (size_t)(b * 16 + h) * 512 * 64;
    const __half* Vp = g_v + (size_t)(b * 16 + h) * 512 * 64;

    // ---- prefetch mask rows for this warp's softmax rows (resolves during
    //      score MMAs). warp wid owns rows 4wid..4wid+3; lane covers
    //      k = 4*lane + 128*i, i=0..3.  Coalesced LDG.32 per (row,i). ----
    uint32_t maskw[16];
    {
        const unsigned char* mrow = g_mask8 + ((size_t)b * 512 + q0) * 512;
#pragma unroll
        for (int rr = 0; rr < 4; rr++)
#pragma unroll
            for (int i = 0; i < 4; i++)
                maskw[rr * 4 + i] = *(const uint32_t*)(
                    mrow + (size_t)(wid * 4 + rr) * 512 + 4 * lane + 128 * i);
    }

    // ---- load Q tile scaled by 1/8 (exact in fp16) ----
    {
        const __half2 sc = __half2half2(__float2half(0.125f));
        int r = tid >> 3, c8 = tid & 7;
        uint4 raw = *(const uint4*)(Q + (size_t)(q0 + r) * 64 + c8 * 8);
        __half2* hp = (__half2*)&raw;
#pragma unroll
        for (int j = 0; j < 4; j++) hp[j] = __hmul2(hp[j], sc);
        *(uint4*)((char*)sQ + r * A_STRIDE + c8 * 16) = raw;
    }

    const int aRow = lane & 15, aColH = (lane >> 4) << 3;
    const int bRow = ((lane >> 4) << 3) + (lane & 7);
    const int bColH = ((lane >> 3) & 1) << 3;

    auto loadKV = [&](const __half* src, int c) {
        char* dst = sh + OFF_KV0 + (c & 1) * KVBUF;
#pragma unroll
        for (int i = 0; i < 4; i++) {
            int g = tid + i * 256;
            int r = g >> 3, cc = g & 7;
            cp16(dst + r * A_STRIDE + cc * 16,
                 src + (size_t)(c * 128 + r) * 64 + cc * 8);
        }
        asm volatile("cp.async.commit_group;\n");
    };

    // ---- scores: S[32,512], K double-buffered ----
    const int wm = wid & 1, wn = wid >> 1;
    loadKV(Kp, 0);
    for (int c = 0; c < 4; c++) {
        __syncthreads();
        if (c < 3) loadKV(Kp, c + 1);
        if (c < 3) { asm volatile("cp.async.wait_group 1;\n"); }
        else       { asm volatile("cp.async.wait_group 0;\n"); }
        __syncthreads();

        const uint32_t kvb = shb + OFF_KV0 + (c & 1) * KVBUF;
        float acc[4][4] = {};
#pragma unroll
        for (int k16 = 0; k16 < 4; k16++) {
            uint32_t a[4], bf[2][4];
            ldm_x4(a, shb + OFF_Q + (wm * 16 + aRow) * A_STRIDE +
                      (k16 * 16 + aColH) * 2);
#pragma unroll
            for (int ni2 = 0; ni2 < 2; ni2++)
                ldm_x4(bf[ni2], kvb + (wn * 32 + ni2 * 16 + bRow) * A_STRIDE +
                               (k16 * 16 + bColH) * 2);
#pragma unroll
            for (int ni = 0; ni < 4; ni++)
                mma_f16(acc[ni], a, bf[ni >> 1][(ni & 1) * 2],
                        bf[ni >> 1][(ni & 1) * 2 + 1]);
        }
        const int row = wm * 16 + lr;
        const int kb = c * 128;
#pragma unroll
        for (int ni = 0; ni < 4; ni++) {
            int col = kb + wn * 32 + ni * 8 + 2 * lc;
            sS[row * SST + col]           = acc[ni][0];
            sS[row * SST + col + 1]       = acc[ni][1];
            sS[(row + 8) * SST + col]     = acc[ni][2];
            sS[(row + 8) * SST + col + 1] = acc[ni][3];
        }
    }

    // ---- prefetch V chunk 0 into buf0 ----
    loadKV(Vp, 0);
    __syncthreads();   // sS complete

    // ---- fused masked softmax + e write. Warp wid owns rows 4wid..4wid+3;
    //      whole warp sweeps one row (lane covers k = 4lane + 128i). ----
    const float NEGINF = __int_as_float(0xff800000);
    float* erow = e_out + (((size_t)(b * 16 + h) * 512) + q0) * 512;
#pragma unroll
    for (int rr = 0; rr < 4; rr++) {
        int r = wid * 4 + rr;
        float* srow = sS + r * SST;
        float4 f[4];
#pragma unroll
        for (int i = 0; i < 4; i++) {
            f[i] = *(const float4*)&srow[4 * lane + 128 * i];
            uint32_t mm = maskw[rr * 4 + i];
            if (mm & 0x000000FFu) f[i].x = NEGINF;
            if (mm & 0x0000FF00u) f[i].y = NEGINF;
            if (mm & 0x00FF0000u) f[i].z = NEGINF;
            if (mm & 0xFF000000u) f[i].w = NEGINF;
        }
        float mx = NEGINF;
#pragma unroll
        for (int i = 0; i < 4; i++) {
            mx = fmaxf(mx, fmaxf(fmaxf(f[i].x, f[i].y), fmaxf(f[i].z, f[i].w)));
        }
#pragma unroll
        for (int o = 16; o; o >>= 1) mx = fmaxf(mx, __shfl_xor_sync(0xffffffffu, mx, o));
        float sum = 0.f;
#pragma unroll
        for (int i = 0; i < 4; i++) {
            f[i].x = __expf(f[i].x - mx);
            f[i].y = __expf(f[i].y - mx);
            f[i].z = __expf(f[i].z - mx);
            f[i].w = __expf(f[i].w - mx);
            sum += (f[i].x + f[i].y) + (f[i].z + f[i].w);
        }
#pragma unroll
        for (int o = 16; o; o >>= 1) sum += __shfl_xor_sync(0xffffffffu, sum, o);
        float inv = 1.f / sum;
        if (lane == 0) sInv[r] = inv;
#pragma unroll
        for (int i = 0; i < 4; i++) {
            *(float4*)&srow[4 * lane + 128 * i] = f[i];   // exp values for EV
            float4 ev = f[i];
            ev.x *= inv; ev.y *= inv; ev.z *= inv; ev.w *= inv;
            __stcs((float4*)(erow + (size_t)r * 512 + 4 * lane + 128 * i), ev);
        }
    }
    __syncthreads();

    // ---- O^T = V^T @ E^T, V double-buffered, E f32->half on the fly ----
    const int wd = wid & 3, wq = wid >> 2;
    const int d0 = wd * 16, qb = wq * 16;
    float oacc[2][4] = {};
    for (int c = 0; c < 4; c++) {
        __syncthreads();
        if (c < 3) loadKV(Vp, c + 1);
        if (c < 3) { asm volatile("cp.async.wait_group 1;\n"); }
        else       { asm volatile("cp.async.wait_group 0;\n"); }
        __syncthreads();

        const uint32_t kvb = shb + OFF_KV0 + (c & 1) * KVBUF;
        const int kb = c * 128;
#pragma unroll
        for (int k16 = 0; k16 < 8; k16++) {
            uint32_t a[4];
            ldm_x4t(a, kvb + (k16 * 16 + bRow) * A_STRIDE + (d0 + bColH) * 2);
#pragma unroll
            for (int ni = 0; ni < 2; ni++) {
                int n = qb + ni * 8 + lr;
                const float* pe = sS + n * SST + kb + k16 * 16 + lc * 2;
                float2 e0 = *(const float2*)pe;
                float2 e1 = *(const float2*)(pe + 8);
                __half2 h0 = __floats2half2_rn(e0.x, e0.y);
                __half2 h1 = __floats2half2_rn(e1.x, e1.y);
                mma_f16(oacc[ni], a, *(const uint32_t*)&h0, *(const uint32_t*)&h1);
            }
        }
    }
    __syncthreads();

    // ---- normalize, stage O[q][d] as half in sQ region, write coalesced ----
    __half* sO = sQ;
#pragma unroll
    for (int ni = 0; ni < 2; ni++) {
        int q = qb + ni * 8 + 2 * lc;
        float i0 = sInv[q], i1 = sInv[q + 1];
        sO[q * 72 + d0 + lr]           = __float2half_rn(oacc[ni][0] * i0);
        sO[(q + 1) * 72 + d0 + lr]     = __float2half_rn(oacc[ni][1] * i1);
        sO[q * 72 + d0 + lr + 8]       = __float2half_rn(oacc[ni][2] * i0);
        sO[(q + 1) * 72 + d0 + lr + 8] = __float2half_rn(oacc[ni][3] * i1);
    }
    __syncthreads();
    {
        int r = tid >> 3, c = tid & 7;
        uint4 v = *(const uint4*)((const char*)sO + r * A_STRIDE + c * 16);
        *(uint4*)(g_ao + ((size_t)(b * 512 + q0 + r)) * 1024 + h * 64 + c * 8) = v;
    }
}

// ---------------- launch ------------------------------------------------------
extern "C" void kernel_launch(void* const* d_in, const int* in_sizes, int n_in,
                              void* d_out, int out_size)
{
    const float*         events = (const float*)d_in[0];
    const unsigned char* mask   = (const unsigned char*)d_in[1];
    const float*         n1a    = (const float*)d_in[2];
    const float*         n1b    = (const float*)d_in[3];
    const float*         wq     = (const float*)d_in[4];
    const float*         bq     = (const float*)d_in[5];
    const float*         wk     = (const float*)d_in[6];
    const float*         bk     = (const float*)d_in[7];
    const float*         wv     = (const float*)d_in[8];
    const float*         bv     = (const float*)d_in[9];
    const float*         wo     = (const float*)d_in[10];
    const float*         bo     = (const float*)d_in[11];
    const float*         n2a    = (const float*)d_in[12];
    const float*         n2b    = (const float*)d_in[13];

    float* out   = (float*)d_out;                       // [16,512,1024]
    float* e_out = out + (size_t)MROWS * 1024;          // [16,16,512,512]

    mask_detect_kernel<<<1, 256>>>(mask);
    prep_kernel<<<4096 + 2048 + MROWS, 256>>>(mask, wq, wk, wv, wo,
                                              events, n1a, n1b);

    cudaFuncSetAttribute(gemm_kernel,
                         cudaFuncAttributeMaxDynamicSharedMemorySize, GEMM_SMEM);
    gemm_kernel<<<dim3(24, MROWS / 128), 256, GEMM_SMEM>>>(1, bq, bk, bv);

    cudaFuncSetAttribute(attn_kernel,
                         cudaFuncAttributeMaxDynamicSharedMemorySize, ATTN_SMEM);
    attn_kernel<<<dim3(16, 16, 16), 256, ATTN_SMEM>>>(e_out);

    gemm_kernel<<<dim3(8, MROWS / 128), 256, GEMM_SMEM>>>(0, bo, nullptr, nullptr);

    norm2_kernel<<<MROWS, 256>>>(n2a, n2b, out);
}